// round 3
// baseline (speedup 1.0000x reference)
#include <cuda_runtime.h>
#include <math.h>

// ---------------- dimensions ----------------
#define N_IMG 17          // 16 exemplars (batch 0..15) + search (batch 16)
#define H0 383
#define W0 287
#define H0P 387           // pad 2
#define W0P 291
#define C1o 64
#define H1 95
#define W1 71
#define P1H 47
#define P1W 35
#define P1HP 51           // pad 2
#define P1WP 39
#define C2o 192
#define H2 47
#define W2 35
#define P2H 23
#define P2W 17
#define P2HP 25           // pad 1
#define P2WP 19
#define C3o 384
#define C4o 256
#define C5o 256
#define H5 23
#define W5 17
#define P5H 11
#define P5W 8
#define MM 88             // 11*8
#define DD 256
#define TT 16
#define TMN 1408          // TT*MM
#define TAILPAD 4096      // over-read safety pad on conv input buffers

typedef unsigned long long ull;

// ---------------- scratch (device globals; no allocation) ----------------
__device__ float g_in [N_IMG*3*H0P*W0P + TAILPAD];
__device__ float g_c1 [N_IMG*C1o*H1*W1];
__device__ float g_p1 [N_IMG*C1o*P1HP*P1WP + TAILPAD];
__device__ float g_c2 [N_IMG*C2o*H2*W2];
__device__ float g_p2 [N_IMG*C2o*P2HP*P2WP + TAILPAD];
__device__ float g_c3 [N_IMG*C3o*P2HP*P2WP + TAILPAD];
__device__ float g_c4 [N_IMG*C4o*P2HP*P2WP + TAILPAD];
__device__ float g_c5 [N_IMG*C5o*H5*W5];
__device__ float g_p5 [N_IMG*C5o*MM];
__device__ float g_xc [256*88];
__device__ float g_v  [256];
__device__ float g_xhat[256*88];
__device__ float g_nodes[TMN*256];
__device__ float g_Y1 [TMN*512];
__device__ float g_S  [16*512];
__device__ float g_h1 [TMN*512];
__device__ float g_Y2 [TMN*256];
__device__ float g_h2 [TMN*256];
__device__ float g_V1 [256*88];
__device__ float g_V1t[88*256];
__device__ float g_Vx [256*88];
__device__ float g_G  [256*88];
__device__ float g_Hh [256*88];
__device__ float g_A2 [88*88];
__device__ float g_xw [88*384];
__device__ float g_c1m[88*384];
__device__ float g_cw [88*256];
__device__ float g_V2t[88*256];

// ---------------- f32x2 helpers ----------------
__device__ __forceinline__ ull pk2(float lo, float hi)
{
    ull r;
    asm("mov.b64 %0, {%1, %2};" : "=l"(r) : "f"(lo), "f"(hi));
    return r;
}
__device__ __forceinline__ void fma2(ull& d, ull a, ull b)
{
    asm("fma.rn.f32x2 %0, %1, %2, %0;" : "+l"(d) : "l"(a), "l"(b));
}
__device__ __forceinline__ void upk2(float& lo, float& hi, ull p)
{
    asm("mov.b64 {%0, %1}, %2;" : "=f"(lo), "=f"(hi) : "l"(p));
}

// ---------------- kernels ----------------

// copy raw images into pad-2 layout
__global__ void pad_copy_k(const float* __restrict__ src, float* __restrict__ dst,
                           int nimg, int boff)
{
    int idx = blockIdx.x * blockDim.x + threadIdx.x;
    int total = nimg * 3 * H0 * W0;
    if (idx >= total) return;
    int w = idx % W0; int t = idx / W0;
    int h = t % H0;   t /= H0;
    int c = t % 3;    int n = t / 3;
    dst[(((size_t)(boff + n) * 3 + c) * H0P + h + 2) * W0P + (w + 2)] = src[idx];
}

// Direct conv + ReLU using packed f32x2 FMA.
// Per thread: 4 output channels x 4 output cols, accumulated as 8 b64 x-pairs.
// Weights staged in SMEM pre-duplicated (w,w) as b64 so a single broadcast
// LDS.64 feeds both FMA halves. Input pre-padded -> no bounds checks in hot loop.
template<int CIN, int K, int S, int CIC>
__global__ __launch_bounds__(128)
void conv4x4f2_k(const float* __restrict__ in, const float* __restrict__ w,
                 const float* __restrict__ bias, float* __restrict__ out,
                 int Cout, int HinP, int WinP, int Hout, int Wout,
                 int HoP, int WoP, int opad)
{
    constexpr int KK = K * K;
    constexpr int RW = K + 3 * S;       // input row width per thread
    __shared__ ull sw[CIC * KK * 4];    // [(ci*KK + kk)*4 + c] = (w,w)

    int cg  = blockIdx.y % (Cout >> 2);
    int n   = blockIdx.y / (Cout >> 2);
    int co0 = cg << 2;

    int wq  = (Wout + 3) >> 2;
    int idx = blockIdx.x * blockDim.x + threadIdx.x;
    bool active = idx < Hout * wq;
    int oh  = active ? idx / wq : 0;
    int ow0 = active ? (idx % wq) << 2 : 0;

    ull acc[4][2];
    #pragma unroll
    for (int c = 0; c < 4; c++) {
        float b = bias[co0 + c];
        acc[c][0] = pk2(b, b);
        acc[c][1] = pk2(b, b);
    }

    const float* inb = in + (size_t)n * CIN * HinP * WinP
                          + (size_t)(oh * S) * WinP + ow0 * S;

    for (int c0 = 0; c0 < CIN; c0 += CIC) {
        // stage duplicated weights for this ci-chunk
        for (int i = threadIdx.x; i < CIC * KK * 4; i += 128) {
            int c  = i & 3;
            int t  = i >> 2;
            int kk = t % KK;
            int ci = t / KK;
            float wv = w[((size_t)(co0 + c) * CIN + c0 + ci) * KK + kk];
            unsigned int b = __float_as_uint(wv);
            sw[i] = (ull)b | ((ull)b << 32);
        }
        __syncthreads();

        if (active) {
            const float* ipc = inb + (size_t)c0 * HinP * WinP;
            for (int ci = 0; ci < CIC; ci++) {
                const float* ip = ipc + (size_t)ci * HinP * WinP;
                const ull* wp = sw + ci * KK * 4;
                #pragma unroll
                for (int kh = 0; kh < K; kh++) {
                    float r[RW];
                    const float* row = ip + kh * WinP;
                    #pragma unroll
                    for (int j = 0; j < RW; j++) r[j] = row[j];
                    #pragma unroll
                    for (int kw = 0; kw < K; kw++) {
                        ull x01 = pk2(r[kw],         r[kw + S]);
                        ull x23 = pk2(r[kw + 2 * S], r[kw + 3 * S]);
                        const ull* wk = wp + (kh * K + kw) * 4;
                        #pragma unroll
                        for (int c = 0; c < 4; c++) {
                            ull w2 = wk[c];
                            fma2(acc[c][0], x01, w2);
                            fma2(acc[c][1], x23, w2);
                        }
                    }
                }
            }
        }
        __syncthreads();
    }

    if (!active) return;
    #pragma unroll
    for (int c = 0; c < 4; c++) {
        float v0, v1, v2, v3;
        upk2(v0, v1, acc[c][0]);
        upk2(v2, v3, acc[c][1]);
        float* op = out + ((size_t)(n * Cout + co0 + c) * HoP + oh + opad) * WoP
                        + ow0 + opad;
        if (ow0 + 0 < Wout) op[0] = fmaxf(v0, 0.f);
        if (ow0 + 1 < Wout) op[1] = fmaxf(v1, 0.f);
        if (ow0 + 2 < Wout) op[2] = fmaxf(v2, 0.f);
        if (ow0 + 3 < Wout) op[3] = fmaxf(v3, 0.f);
    }
}

// 3x3 stride-2 VALID maxpool, output written into (possibly padded) buffer
__global__ void maxpool_k(const float* __restrict__ in, float* __restrict__ out,
                          int NC, int Hin, int Win, int Ho, int Wo,
                          int HoP, int WoP, int opad)
{
    int idx = blockIdx.x * blockDim.x + threadIdx.x;
    int total = NC * Ho * Wo;
    if (idx >= total) return;
    int ow = idx % Wo; int t = idx / Wo;
    int oh = t % Ho;   int nc = t / Ho;
    const float* ip = in + ((size_t)nc * Hin + oh * 2) * Win + ow * 2;
    float m = -INFINITY;
    #pragma unroll
    for (int kh = 0; kh < 3; kh++)
        #pragma unroll
        for (int kw = 0; kw < 3; kw++)
            m = fmaxf(m, ip[kh * Win + kw]);
    out[((size_t)nc * HoP + oh + opad) * WoP + ow + opad] = m;
}

// conv1d(k=3,p=1) over Xf [256,88]
__global__ void cd_conv_k(const float* __restrict__ Xf, const float* __restrict__ wcd,
                          const float* __restrict__ bcd, float* __restrict__ xc)
{
    int p = blockIdx.x;     // 0..87
    int o = threadIdx.x;    // 0..255
    float acc = bcd[o];
    for (int i = 0; i < 256; i++) {
        const float* wr = wcd + (o * 256 + i) * 3;
        const float* xr = Xf + i * 88;
        if (p > 0)  acc += xr[p - 1] * wr[0];
        acc += xr[p] * wr[1];
        if (p < 87) acc += xr[p + 1] * wr[2];
    }
    xc[o * 88 + p] = acc;
}

__global__ void cd_max_k(const float* __restrict__ xc, float* __restrict__ v)
{
    int o = threadIdx.x;
    float m = -INFINITY;
    for (int p = 0; p < 88; p++) m = fmaxf(m, xc[o * 88 + p]);
    v[o] = m;
}

// X_hat[o,k] = sum_i v[i]*wt[i,o,k] + bt[o]
__global__ void xhat_k(const float* __restrict__ v, const float* __restrict__ wt,
                       const float* __restrict__ bt, float* __restrict__ xhat)
{
    __shared__ float sv[256];
    int o = blockIdx.x;     // 0..255
    int k = threadIdx.x;    // 0..87
    for (int i = threadIdx.x; i < 256; i += blockDim.x) sv[i] = v[i];
    __syncthreads();
    float acc = bt[o];
    for (int i = 0; i < 256; i++)
        acc += sv[i] * wt[((size_t)i * 256 + o) * 88 + k];
    xhat[o * 88 + k] = acc;
}

// nodes[m*16+t, d] = p5[t][d][m]
__global__ void gather_nodes_k(const float* __restrict__ p5, float* __restrict__ nodes)
{
    int idx = blockIdx.x * blockDim.x + threadIdx.x;
    if (idx >= TMN * 256) return;
    int d = idx % 256;
    int n = idx / 256;
    int t = n % 16, m = n / 16;
    nodes[idx] = p5[((size_t)t * 256 + d) * 88 + m];
}

// register-blocked SGEMM: C[M,N] = A[M,K] @ B[K,N]
// 64x64 block tile, 4x4 per thread, 256 threads, k-tile 16.
// flags: 1=bias per row, 2=bias per col, 4=leaky relu
__global__ __launch_bounds__(256)
void rbgemm_k(const float* __restrict__ A, const float* __restrict__ B,
              const float* __restrict__ bias, float* __restrict__ C,
              int M, int N, int K, int flags)
{
    __shared__ float As[16][65];
    __shared__ float Bs[16][64];
    int tid = threadIdx.x;
    int tx = tid & 15;          // 0..15 -> N
    int ty = tid >> 4;          // 0..15 -> M
    int m0 = blockIdx.y * 64;
    int n0 = blockIdx.x * 64;

    float acc[4][4] = {};

    for (int k0 = 0; k0 < K; k0 += 16) {
        #pragma unroll
        for (int i = 0; i < 4; i++) {
            int e  = tid + i * 256;
            int kk = e & 15;
            int mm = e >> 4;
            int gm = m0 + mm, gk = k0 + kk;
            As[kk][mm] = (gm < M && gk < K) ? A[(size_t)gm * K + gk] : 0.f;
        }
        #pragma unroll
        for (int i = 0; i < 4; i++) {
            int nn = tid & 63;
            int kk = (tid >> 6) + i * 4;
            int gk = k0 + kk, gn = n0 + nn;
            Bs[kk][nn] = (gk < K && gn < N) ? B[(size_t)gk * N + gn] : 0.f;
        }
        __syncthreads();
        #pragma unroll
        for (int kk = 0; kk < 16; kk++) {
            float ra[4], rb[4];
            #pragma unroll
            for (int i = 0; i < 4; i++) ra[i] = As[kk][ty * 4 + i];
            #pragma unroll
            for (int j = 0; j < 4; j++) rb[j] = Bs[kk][tx * 4 + j];
            #pragma unroll
            for (int i = 0; i < 4; i++)
                #pragma unroll
                for (int j = 0; j < 4; j++)
                    acc[i][j] += ra[i] * rb[j];
        }
        __syncthreads();
    }

    #pragma unroll
    for (int i = 0; i < 4; i++) {
        int gm = m0 + ty * 4 + i;
        if (gm >= M) continue;
        #pragma unroll
        for (int j = 0; j < 4; j++) {
            int gn = n0 + tx * 4 + j;
            if (gn >= N) continue;
            float v = acc[i][j];
            if (flags & 1) v += bias[gm];
            if (flags & 2) v += bias[gn];
            if (flags & 4) v = v >= 0.f ? v : 0.01f * v;
            C[(size_t)gm * N + gn] = v;
        }
    }
}

// S[t,f] = sum_m Y[(m*16+t),f]
__global__ void a1_reduce_k(const float* __restrict__ Y, float* __restrict__ S, int F)
{
    int f = blockIdx.x * blockDim.x + threadIdx.x;
    int t = blockIdx.y;
    if (f >= F) return;
    float s = 0.f;
    for (int m = 0; m < 88; m++) s += Y[(size_t)(m * 16 + t) * F + f];
    S[t * F + f] = s;
}

// h[n,f] = lrelu(S[t,f] - (t==0)*Y[n,f] + bias[f])
__global__ void a1_apply_k(const float* __restrict__ Y, const float* __restrict__ S,
                           const float* __restrict__ bias, float* __restrict__ h, int F)
{
    int idx = blockIdx.x * blockDim.x + threadIdx.x;
    if (idx >= TMN * F) return;
    int f = idx % F;
    int n = idx / F;
    int t = n % 16;
    float val = S[t * F + f] + bias[f];
    if (t == 0) val -= Y[idx];
    h[idx] = val >= 0.f ? val : 0.01f * val;
}

// V1[d,m]=max_t h2[(m*16+t),d]; V1t[m,d]=V1; Vx = V1 + xhat
__global__ void v1_k(const float* __restrict__ h2, const float* __restrict__ xhat,
                     float* __restrict__ V1, float* __restrict__ V1t, float* __restrict__ Vx)
{
    int idx = blockIdx.x * blockDim.x + threadIdx.x;
    if (idx >= 256 * 88) return;
    int d = idx % 256;
    int m = idx / 256;
    float mx = -INFINITY;
    #pragma unroll
    for (int t = 0; t < 16; t++) mx = fmaxf(mx, h2[(size_t)(m * 16 + t) * 256 + d]);
    V1[d * 88 + m] = mx;
    V1t[m * 256 + d] = mx;
    Vx[d * 88 + m] = mx + xhat[d * 88 + m];
}

// A2[j,:] = softmax_i( sum_d Hh[d,j]*G[d,i] )
__global__ void attn_k(const float* __restrict__ G, const float* __restrict__ Hh,
                       float* __restrict__ A2)
{
    __shared__ float red[128];
    int j = blockIdx.x;
    int i = threadIdx.x;
    float s = 0.f;
    if (i < 88) {
        for (int d = 0; d < 256; d++) s += Hh[d * 88 + j] * G[d * 88 + i];
    }
    red[i] = (i < 88) ? s : -INFINITY;
    __syncthreads();
    for (int st = 64; st > 0; st >>= 1) {
        if (i < st) red[i] = fmaxf(red[i], red[i + st]);
        __syncthreads();
    }
    float mx = red[0];
    __syncthreads();
    float e = (i < 88) ? expf(s - mx) : 0.f;
    red[i] = e;
    __syncthreads();
    for (int st = 64; st > 0; st >>= 1) {
        if (i < st) red[i] += red[i + st];
        __syncthreads();
    }
    float sum = red[0];
    if (i < 88) A2[j * 88 + i] = e / sum;
}

// R = sum_{d,m} Xf[d,m] * V2t[m,d]
__global__ void final_dot_k(const float* __restrict__ Xf, const float* __restrict__ V2t,
                            float* __restrict__ out)
{
    __shared__ float red[256];
    float acc = 0.f;
    for (int e = threadIdx.x; e < 256 * 88; e += 256) {
        int d = e / 88, m = e % 88;
        acc += Xf[e] * V2t[m * 256 + d];
    }
    red[threadIdx.x] = acc;
    __syncthreads();
    for (int st = 128; st > 0; st >>= 1) {
        if (threadIdx.x < st) red[threadIdx.x] += red[threadIdx.x + st];
        __syncthreads();
    }
    if (threadIdx.x == 0) out[0] = red[0];
}

// ---------------- host ----------------
static float* symaddr(const void* s)
{
    void* p = nullptr;
    cudaGetSymbolAddress(&p, s);
    return (float*)p;
}

extern "C" void kernel_launch(void* const* d_in, const int* in_sizes, int n_in,
                              void* d_out, int out_size)
{
    const float* search    = (const float*)d_in[0];
    const float* exemplars = (const float*)d_in[1];
    const float* aw1 = (const float*)d_in[2];  const float* ab1 = (const float*)d_in[3];
    const float* aw2 = (const float*)d_in[4];  const float* ab2 = (const float*)d_in[5];
    const float* aw3 = (const float*)d_in[6];  const float* ab3 = (const float*)d_in[7];
    const float* aw4 = (const float*)d_in[8];  const float* ab4 = (const float*)d_in[9];
    const float* aw5 = (const float*)d_in[10]; const float* ab5 = (const float*)d_in[11];
    const float* wcd = (const float*)d_in[12]; const float* bcd = (const float*)d_in[13];
    const float* wt  = (const float*)d_in[14]; const float* bt  = (const float*)d_in[15];
    const float* ws1 = (const float*)d_in[16]; const float* bs1 = (const float*)d_in[17];
    const float* ws2 = (const float*)d_in[18]; const float* bs2 = (const float*)d_in[19];
    const float* wg  = (const float*)d_in[20]; const float* bg  = (const float*)d_in[21];
    const float* wh  = (const float*)d_in[22]; const float* bh  = (const float*)d_in[23];
    const float* wc1 = (const float*)d_in[24]; const float* bc1 = (const float*)d_in[25];
    const float* wc2 = (const float*)d_in[26]; const float* bc2 = (const float*)d_in[27];

    float* p_in  = symaddr(g_in);
    float* p_c1  = symaddr(g_c1);
    float* p_p1  = symaddr(g_p1);
    float* p_c2  = symaddr(g_c2);
    float* p_p2  = symaddr(g_p2);
    float* p_c3  = symaddr(g_c3);
    float* p_c4  = symaddr(g_c4);
    float* p_c5  = symaddr(g_c5);
    float* p_p5  = symaddr(g_p5);
    float* p_xc  = symaddr(g_xc);
    float* p_v   = symaddr(g_v);
    float* p_xh  = symaddr(g_xhat);
    float* p_nd  = symaddr(g_nodes);
    float* p_Y1  = symaddr(g_Y1);
    float* p_S   = symaddr(g_S);
    float* p_h1  = symaddr(g_h1);
    float* p_Y2  = symaddr(g_Y2);
    float* p_h2  = symaddr(g_h2);
    float* p_V1  = symaddr(g_V1);
    float* p_V1t = symaddr(g_V1t);
    float* p_Vx  = symaddr(g_Vx);
    float* p_G   = symaddr(g_G);
    float* p_Hh  = symaddr(g_Hh);
    float* p_A2  = symaddr(g_A2);
    float* p_xw  = symaddr(g_xw);
    float* p_c1m = symaddr(g_c1m);
    float* p_cw  = symaddr(g_cw);
    float* p_V2t = symaddr(g_V2t);

    // zero padded buffers (borders must be 0 every replay)
    cudaMemsetAsync(p_in, 0, sizeof(float) * ((size_t)N_IMG * 3 * H0P * W0P + TAILPAD), 0);
    cudaMemsetAsync(p_p1, 0, sizeof(float) * ((size_t)N_IMG * C1o * P1HP * P1WP + TAILPAD), 0);
    cudaMemsetAsync(p_p2, 0, sizeof(float) * ((size_t)N_IMG * C2o * P2HP * P2WP + TAILPAD), 0);
    cudaMemsetAsync(p_c3, 0, sizeof(float) * ((size_t)N_IMG * C3o * P2HP * P2WP + TAILPAD), 0);
    cudaMemsetAsync(p_c4, 0, sizeof(float) * ((size_t)N_IMG * C4o * P2HP * P2WP + TAILPAD), 0);

    // assemble padded input batch: exemplars first (0..15), search last (16)
    {
        int tot = 16 * 3 * H0 * W0;
        pad_copy_k<<<(tot + 127) / 128, 128>>>(exemplars, p_in, 16, 0);
        tot = 3 * H0 * W0;
        pad_copy_k<<<(tot + 127) / 128, 128>>>(search, p_in, 1, 16);
    }

    // ---- AlexNet features ----
    {   // conv1: 3->64, k11 s4
        int wq = (W1 + 3) / 4, sp = H1 * wq;
        conv4x4f2_k<3, 11, 4, 3><<<dim3((sp + 127) / 128, N_IMG * (C1o / 4)), 128>>>(
            p_in, aw1, ab1, p_c1, C1o, H0P, W0P, H1, W1, H1, W1, 0);
    }
    {   // pool1 -> padded2 buffer
        int tot = N_IMG * C1o * P1H * P1W;
        maxpool_k<<<(tot + 127) / 128, 128>>>(p_c1, p_p1, N_IMG * C1o, H1, W1, P1H, P1W, P1HP, P1WP, 2);
    }
    {   // conv2: 64->192, k5 s1
        int wq = (W2 + 3) / 4, sp = H2 * wq;
        conv4x4f2_k<64, 5, 1, 32><<<dim3((sp + 127) / 128, N_IMG * (C2o / 4)), 128>>>(
            p_p1, aw2, ab2, p_c2, C2o, P1HP, P1WP, H2, W2, H2, W2, 0);
    }
    {   // pool2 -> padded1 buffer
        int tot = N_IMG * C2o * P2H * P2W;
        maxpool_k<<<(tot + 127) / 128, 128>>>(p_c2, p_p2, N_IMG * C2o, H2, W2, P2H, P2W, P2HP, P2WP, 1);
    }
    {   // conv3: 192->384, out padded1
        int wq = (P2W + 3) / 4, sp = P2H * wq;
        conv4x4f2_k<192, 3, 1, 64><<<dim3((sp + 127) / 128, N_IMG * (C3o / 4)), 128>>>(
            p_p2, aw3, ab3, p_c3, C3o, P2HP, P2WP, P2H, P2W, P2HP, P2WP, 1);
    }
    {   // conv4: 384->256, out padded1
        int wq = (P2W + 3) / 4, sp = P2H * wq;
        conv4x4f2_k<384, 3, 1, 64><<<dim3((sp + 127) / 128, N_IMG * (C4o / 4)), 128>>>(
            p_c3, aw4, ab4, p_c4, C4o, P2HP, P2WP, P2H, P2W, P2HP, P2WP, 1);
    }
    {   // conv5: 256->256, out unpadded
        int wq = (P2W + 3) / 4, sp = P2H * wq;
        conv4x4f2_k<256, 3, 1, 64><<<dim3((sp + 127) / 128, N_IMG * (C5o / 4)), 128>>>(
            p_c4, aw5, ab5, p_c5, C5o, P2HP, P2WP, H5, W5, H5, W5, 0);
    }
    {   // pool5 -> [17,256,11,8]
        int tot = N_IMG * C5o * P5H * P5W;
        maxpool_k<<<(tot + 127) / 128, 128>>>(p_c5, p_p5, N_IMG * C5o, H5, W5, P5H, P5W, P5H, P5W, 0);
    }

    const float* Xf = p_p5 + (size_t)16 * 256 * 88;   // search features [256,88]

    // ---- conv_deconv branch ----
    cd_conv_k<<<88, 256>>>(Xf, wcd, bcd, p_xc);
    cd_max_k<<<1, 256>>>(p_xc, p_v);
    xhat_k<<<256, 88>>>(p_v, wt, bt, p_xh);

    // ---- spatiotemporal GCN ----
    gather_nodes_k<<<(TMN * 256 + 127) / 128, 128>>>(p_p5, p_nd);
    rbgemm_k<<<dim3(512 / 64, TMN / 64), 256>>>(p_nd, ws1, nullptr, p_Y1, TMN, 512, 256, 0);
    a1_reduce_k<<<dim3(4, 16), 128>>>(p_Y1, p_S, 512);
    a1_apply_k<<<(TMN * 512 + 255) / 256, 256>>>(p_Y1, p_S, bs1, p_h1, 512);
    rbgemm_k<<<dim3(256 / 64, TMN / 64), 256>>>(p_h1, ws2, nullptr, p_Y2, TMN, 256, 512, 0);
    a1_reduce_k<<<dim3(2, 16), 128>>>(p_Y2, p_S, 256);
    a1_apply_k<<<(TMN * 256 + 255) / 256, 256>>>(p_Y2, p_S, bs2, p_h2, 256);
    v1_k<<<(256 * 88 + 255) / 256, 256>>>(p_h2, p_xh, p_V1, p_V1t, p_Vx);

    // ---- dynamic cross-track graph ----
    rbgemm_k<<<dim3((88 + 63) / 64, 256 / 64), 256>>>(wg, p_Vx, bg, p_G, 256, 88, 256, 1);
    rbgemm_k<<<dim3((88 + 63) / 64, 256 / 64), 256>>>(wh, p_Vx, bh, p_Hh, 256, 88, 256, 1);
    attn_k<<<88, 128>>>(p_G, p_Hh, p_A2);

    // ---- ct GCN ----
    rbgemm_k<<<dim3(384 / 64, (88 + 63) / 64), 256>>>(p_V1t, wc1, nullptr, p_xw, 88, 384, 256, 0);
    rbgemm_k<<<dim3(384 / 64, (88 + 63) / 64), 256>>>(p_A2, p_xw, bc1, p_c1m, 88, 384, 88, 2 | 4);
    rbgemm_k<<<dim3(256 / 64, (88 + 63) / 64), 256>>>(p_c1m, wc2, nullptr, p_cw, 88, 256, 384, 0);
    rbgemm_k<<<dim3(256 / 64, (88 + 63) / 64), 256>>>(p_A2, p_cw, bc2, p_V2t, 88, 256, 88, 2 | 4);

    // ---- final correlation ----
    final_dot_k<<<1, 256>>>(Xf, p_V2t, (float*)d_out);
}

// round 6
// speedup vs baseline: 1.2252x; 1.2252x over previous
#include <cuda_runtime.h>
#include <cuda_bf16.h>
#include <cstdint>
#include <math.h>

// ---------------- dimensions ----------------
#define N_IMG 17
#define H0 383
#define W0 287
#define H0P 387
#define W0P 291
#define C1o 64
#define H1 95
#define W1 71
#define P1H 47
#define P1W 35
#define P1HP 51
#define P1WP 39
#define C2o 192
#define H2 47
#define W2 35
#define P2H 23
#define P2W 17
#define P2HP 25
#define P2WP 19
#define C3o 384
#define C4o 256
#define C5o 256
#define H5 23
#define W5 17
#define P5H 11
#define P5W 8
#define MM 88
#define DD 256
#define TT 16
#define TMN 1408
#define TAILPAD 4096

// ---------------- scratch (device globals; no allocation) ----------------
__device__ float g_in [N_IMG*3*H0P*W0P + TAILPAD];
__device__ float g_c1 [N_IMG*C1o*H1*W1];
__device__ float g_p1 [N_IMG*C1o*P1HP*P1WP + TAILPAD];
__device__ float g_c2 [N_IMG*C2o*H2*W2];
__device__ float g_p2 [N_IMG*C2o*P2HP*P2WP + TAILPAD];
__device__ float g_c3 [N_IMG*C3o*P2HP*P2WP + TAILPAD];
__device__ float g_c4 [N_IMG*C4o*P2HP*P2WP + TAILPAD];
__device__ float g_c5 [N_IMG*C5o*H5*W5];
__device__ float g_p5 [N_IMG*C5o*MM];
__device__ float g_xc [256*88];
__device__ float g_v  [256];
__device__ float g_xhat[256*88];
__device__ float g_nodes[TMN*256];
__device__ float g_Y1 [TMN*512];
__device__ float g_S  [16*512];
__device__ float g_h1 [TMN*512];
__device__ float g_Y2 [TMN*256];
__device__ float g_h2 [TMN*256];
__device__ float g_V1 [256*88];
__device__ float g_V1t[88*256];
__device__ float g_Vx [256*88];
__device__ float g_G  [256*88];
__device__ float g_Hh [256*88];
__device__ float g_A2 [88*88];
__device__ float g_xw [88*384];
__device__ float g_c1m[88*384];
__device__ float g_cw [88*256];
__device__ float g_V2t[88*256];

// bf16 split matrices for tensor-core conv GEMMs
__device__ __nv_bfloat16 g_Ahi[384*3456];
__device__ __nv_bfloat16 g_Alo[384*3456];
__device__ __nv_bfloat16 g_Bhi[44800000];
__device__ __nv_bfloat16 g_Blo[44800000];

// ---------------- mma helpers (baseline PTX, sm_80+) ----------------
__device__ __forceinline__ uint32_t smem_u32(const void* p)
{
    uint32_t a;
    asm("{ .reg .u64 t; cvta.to.shared.u64 t, %1; cvt.u32.u64 %0, t; }" : "=r"(a) : "l"(p));
    return a;
}
__device__ __forceinline__ void ldsm_x4(uint32_t& r0, uint32_t& r1, uint32_t& r2, uint32_t& r3,
                                        uint32_t addr)
{
    asm volatile("ldmatrix.sync.aligned.m8n8.x4.shared.b16 {%0,%1,%2,%3}, [%4];"
                 : "=r"(r0), "=r"(r1), "=r"(r2), "=r"(r3) : "r"(addr));
}
__device__ __forceinline__ void mma16816(float* d, const uint32_t* a, uint32_t b0, uint32_t b1)
{
    asm volatile("mma.sync.aligned.m16n8k16.row.col.f32.bf16.bf16.f32 "
                 "{%0,%1,%2,%3}, {%4,%5,%6,%7}, {%8,%9}, {%0,%1,%2,%3};"
                 : "+f"(d[0]), "+f"(d[1]), "+f"(d[2]), "+f"(d[3])
                 : "r"(a[0]), "r"(a[1]), "r"(a[2]), "r"(a[3]), "r"(b0), "r"(b1));
}

// ---------------- prep kernels ----------------
__global__ void wsplit_k(const float* __restrict__ w, __nv_bfloat16* __restrict__ hi,
                         __nv_bfloat16* __restrict__ lo, int n)
{
    int i = blockIdx.x * blockDim.x + threadIdx.x;
    if (i >= n) return;
    float x = w[i];
    __nv_bfloat16 h = __float2bfloat16_rn(x);
    hi[i] = h;
    lo[i] = __float2bfloat16_rn(x - __bfloat162float(h));
}

// im2col + bf16 split. B[p,k], k = ci*KD*KD + kh*KD + kw; input pre-padded.
__global__ void im2col_k(const float* __restrict__ in,
                         __nv_bfloat16* __restrict__ bhi, __nv_bfloat16* __restrict__ blo,
                         int CIN, int KD, int HinP, int WinP,
                         int Hout, int Wout, int Ktot, int Npix)
{
    long long idx = (long long)blockIdx.x * blockDim.x + threadIdx.x;
    long long total = (long long)Npix * Ktot;
    if (idx >= total) return;
    int p = (int)(idx / Ktot);
    int k = (int)(idx - (long long)p * Ktot);
    int KK = KD * KD;
    int ci = k / KK;
    int r  = k - ci * KK;
    int kh = r / KD;
    int kw = r - kh * KD;
    int HW = Hout * Wout;
    int img = p / HW;
    int rr  = p - img * HW;
    int oh  = rr / Wout;
    int ow  = rr - oh * Wout;
    float x = in[((size_t)(img * CIN + ci) * HinP + oh + kh) * WinP + ow + kw];
    __nv_bfloat16 h = __float2bfloat16_rn(x);
    bhi[idx] = h;
    blo[idx] = __float2bfloat16_rn(x - __bfloat162float(h));
}

// ---------------- tensor-core conv GEMM (mma.sync bf16, split-K precision) ----------------
#define ASTR 72     // SMEM row stride in bf16 (16B aligned, conflict-free ldmatrix)
__global__ void __launch_bounds__(256)
mmaconv_k(const __nv_bfloat16* __restrict__ Ahi, const __nv_bfloat16* __restrict__ Alo,
          const __nv_bfloat16* __restrict__ Bhi, const __nv_bfloat16* __restrict__ Blo,
          const float* __restrict__ bias, float* __restrict__ out,
          int M, int Npix, int K, int Hout, int Wout,
          int HoP, int WoP, int opad)
{
    __shared__ __nv_bfloat16 sA[128 * ASTR];
    __shared__ __nv_bfloat16 sB[64 * ASTR];

    int tid  = threadIdx.x;
    int lane = tid & 31;
    int wid  = tid >> 5;
    int wm   = wid & 3;          // warp M index (0..3) -> 32 rows
    int wn   = wid >> 2;         // warp N index (0..1) -> 32 cols

    int m0 = blockIdx.y * 128;
    int n0 = blockIdx.x * 64;

    float d[2][4][4];
    #pragma unroll
    for (int i = 0; i < 2; i++)
        #pragma unroll
        for (int j = 0; j < 4; j++)
            #pragma unroll
            for (int r = 0; r < 4; r++) d[i][j][r] = 0.f;

    uint32_t sAbase = smem_u32(sA);
    uint32_t sBbase = smem_u32(sB);
    int aj = lane >> 3, ar = lane & 7;
    // A: matrix j -> rows (j%2)*8, k + (j/2)*8
    uint32_t aAddrOff = (uint32_t)(((aj & 1) * 8 + ar) * ASTR + (aj >> 1) * 8) * 2;
    // B: matrix j -> rows (j/2)*8, k + (j%2)*8
    uint32_t bAddrOff = (uint32_t)(((aj >> 1) * 8 + ar) * ASTR + (aj & 1) * 8) * 2;

    int per = K >> 6;            // 64-wide K chunks per segment
    int itK = 3 * per;

    for (int it = 0; it < itK; it++) {
        int seg = it / per;
        int kof = (it - seg * per) << 6;
        const __nv_bfloat16* As = (seg < 2) ? Ahi : Alo;
        const __nv_bfloat16* Bs = (seg == 1) ? Blo : Bhi;

        // load A tile 128x64 bf16 = 1024 uint4, 4 per thread
        #pragma unroll
        for (int j = 0; j < 4; j++) {
            int i = tid + j * 256;
            int row = i >> 3, q = i & 7;
            uint4 v = make_uint4(0, 0, 0, 0);
            if (m0 + row < M)
                v = *(const uint4*)(As + (size_t)(m0 + row) * K + kof + q * 8);
            *(uint4*)(sA + row * ASTR + q * 8) = v;
        }
        // load B tile 64x64 bf16 = 512 uint4, 2 per thread
        #pragma unroll
        for (int j = 0; j < 2; j++) {
            int i = tid + j * 256;
            int row = i >> 3, q = i & 7;
            uint4 v = make_uint4(0, 0, 0, 0);
            if (n0 + row < Npix)
                v = *(const uint4*)(Bs + (size_t)(n0 + row) * K + kof + q * 8);
            *(uint4*)(sB + row * ASTR + q * 8) = v;
        }
        __syncthreads();

        #pragma unroll
        for (int kk = 0; kk < 4; kk++) {
            uint32_t a[2][4];
            #pragma unroll
            for (int mi = 0; mi < 2; mi++) {
                uint32_t ad = sAbase + aAddrOff
                            + (uint32_t)((wm * 32 + mi * 16) * ASTR + kk * 16) * 2;
                ldsm_x4(a[mi][0], a[mi][1], a[mi][2], a[mi][3], ad);
            }
            uint32_t b[4][2];
            #pragma unroll
            for (int q = 0; q < 2; q++) {
                uint32_t bd = sBbase + bAddrOff
                            + (uint32_t)((wn * 32 + q * 16) * ASTR + kk * 16) * 2;
                uint32_t r0, r1, r2, r3;
                ldsm_x4(r0, r1, r2, r3, bd);
                b[q * 2][0] = r0;  b[q * 2][1] = r1;
                b[q * 2 + 1][0] = r2;  b[q * 2 + 1][1] = r3;
            }
            #pragma unroll
            for (int mi = 0; mi < 2; mi++)
                #pragma unroll
                for (int nj = 0; nj < 4; nj++)
                    mma16816(d[mi][nj], a[mi], b[nj][0], b[nj][1]);
        }
        __syncthreads();
    }

    // epilogue: bias + ReLU + NCHW scatter
    int HW = Hout * Wout;
    #pragma unroll
    for (int mi = 0; mi < 2; mi++) {
        #pragma unroll
        for (int r2 = 0; r2 < 2; r2++) {
            int co = m0 + wm * 32 + mi * 16 + (lane >> 2) + r2 * 8;
            if (co >= M) continue;
            float bv = bias[co];
            #pragma unroll
            for (int nj = 0; nj < 4; nj++) {
                #pragma unroll
                for (int c = 0; c < 2; c++) {
                    int p = n0 + wn * 32 + nj * 8 + (lane & 3) * 2 + c;
                    if (p >= Npix) continue;
                    float v = d[mi][nj][r2 * 2 + c] + bv;
                    int img = p / HW;
                    int rr  = p - img * HW;
                    int oh  = rr / Wout;
                    int ow  = rr - oh * Wout;
                    out[((size_t)(img * M + co) * HoP + oh + opad) * WoP + ow + opad]
                        = fmaxf(v, 0.f);
                }
            }
        }
    }
}

// ---------------- scalar kernels (conv1 + rest of network) ----------------

__global__ void pad_copy_k(const float* __restrict__ src, float* __restrict__ dst,
                           int nimg, int boff)
{
    int idx = blockIdx.x * blockDim.x + threadIdx.x;
    int total = nimg * 3 * H0 * W0;
    if (idx >= total) return;
    int w = idx % W0; int t = idx / W0;
    int h = t % H0;   t /= H0;
    int c = t % 3;    int n = t / 3;
    dst[(((size_t)(boff + n) * 3 + c) * H0P + h + 2) * W0P + (w + 2)] = src[idx];
}

template<int CIN, int K, int S, int CIC>
__global__ __launch_bounds__(128)
void conv4x4_k(const float* __restrict__ in, const float* __restrict__ w,
               const float* __restrict__ bias, float* __restrict__ out,
               int Cout, int HinP, int WinP, int Hout, int Wout,
               int HoP, int WoP, int opad)
{
    constexpr int KK = K * K;
    constexpr int RW = K + 3 * S;
    __shared__ float sw[CIC * 4 * KK];

    int cg  = blockIdx.y % (Cout >> 2);
    int n   = blockIdx.y / (Cout >> 2);
    int co0 = cg << 2;

    int wq  = (Wout + 3) >> 2;
    int idx = blockIdx.x * blockDim.x + threadIdx.x;
    bool active = idx < Hout * wq;
    int oh  = active ? idx / wq : 0;
    int ow0 = active ? (idx % wq) << 2 : 0;

    float acc[4][4];
    #pragma unroll
    for (int c = 0; c < 4; c++) {
        float b = bias[co0 + c];
        #pragma unroll
        for (int x = 0; x < 4; x++) acc[c][x] = b;
    }

    const float* inb = in + (size_t)n * CIN * HinP * WinP
                          + (size_t)(oh * S) * WinP + ow0 * S;

    for (int c0 = 0; c0 < CIN; c0 += CIC) {
        for (int i = threadIdx.x; i < CIC * 4 * KK; i += 128) {
            int kk = i % KK;
            int t  = i / KK;
            int c  = t & 3;
            int ci = t >> 2;
            sw[i] = w[((size_t)(co0 + c) * CIN + c0 + ci) * KK + kk];
        }
        __syncthreads();

        if (active) {
            const float* ipc = inb + (size_t)c0 * HinP * WinP;
            for (int ci = 0; ci < CIC; ci++) {
                const float* ip = ipc + (size_t)ci * HinP * WinP;
                const float* wp = sw + ci * 4 * KK;
                #pragma unroll
                for (int kh = 0; kh < K; kh++) {
                    float r[RW];
                    const float* row = ip + kh * WinP;
                    #pragma unroll
                    for (int j = 0; j < RW; j++) r[j] = row[j];
                    #pragma unroll
                    for (int kw = 0; kw < K; kw++) {
                        float w0 = wp[0 * KK + kh * K + kw];
                        float w1 = wp[1 * KK + kh * K + kw];
                        float w2 = wp[2 * KK + kh * K + kw];
                        float w3 = wp[3 * KK + kh * K + kw];
                        #pragma unroll
                        for (int x = 0; x < 4; x++) {
                            float xv = r[kw + x * S];
                            acc[0][x] += xv * w0;
                            acc[1][x] += xv * w1;
                            acc[2][x] += xv * w2;
                            acc[3][x] += xv * w3;
                        }
                    }
                }
            }
        }
        __syncthreads();
    }

    if (!active) return;
    #pragma unroll
    for (int c = 0; c < 4; c++) {
        float* op = out + ((size_t)(n * Cout + co0 + c) * HoP + oh + opad) * WoP
                        + ow0 + opad;
        #pragma unroll
        for (int x = 0; x < 4; x++)
            if (ow0 + x < Wout) op[x] = fmaxf(acc[c][x], 0.f);
    }
}

__global__ void maxpool_k(const float* __restrict__ in, float* __restrict__ out,
                          int NC, int Hin, int Win, int Ho, int Wo,
                          int HoP, int WoP, int opad)
{
    int idx = blockIdx.x * blockDim.x + threadIdx.x;
    int total = NC * Ho * Wo;
    if (idx >= total) return;
    int ow = idx % Wo; int t = idx / Wo;
    int oh = t % Ho;   int nc = t / Ho;
    const float* ip = in + ((size_t)nc * Hin + oh * 2) * Win + ow * 2;
    float m = -INFINITY;
    #pragma unroll
    for (int kh = 0; kh < 3; kh++)
        #pragma unroll
        for (int kw = 0; kw < 3; kw++)
            m = fmaxf(m, ip[kh * Win + kw]);
    out[((size_t)nc * HoP + oh + opad) * WoP + ow + opad] = m;
}

__global__ void cd_conv_k(const float* __restrict__ Xf, const float* __restrict__ wcd,
                          const float* __restrict__ bcd, float* __restrict__ xc)
{
    int p = blockIdx.x;
    int o = threadIdx.x;
    float acc = bcd[o];
    for (int i = 0; i < 256; i++) {
        const float* wr = wcd + (o * 256 + i) * 3;
        const float* xr = Xf + i * 88;
        if (p > 0)  acc += xr[p - 1] * wr[0];
        acc += xr[p] * wr[1];
        if (p < 87) acc += xr[p + 1] * wr[2];
    }
    xc[o * 88 + p] = acc;
}

__global__ void cd_max_k(const float* __restrict__ xc, float* __restrict__ v)
{
    int o = threadIdx.x;
    float m = -INFINITY;
    for (int p = 0; p < 88; p++) m = fmaxf(m, xc[o * 88 + p]);
    v[o] = m;
}

__global__ void xhat_k(const float* __restrict__ v, const float* __restrict__ wt,
                       const float* __restrict__ bt, float* __restrict__ xhat)
{
    __shared__ float sv[256];
    int o = blockIdx.x;
    int k = threadIdx.x;
    for (int i = threadIdx.x; i < 256; i += blockDim.x) sv[i] = v[i];
    __syncthreads();
    float acc = bt[o];
    for (int i = 0; i < 256; i++)
        acc += sv[i] * wt[((size_t)i * 256 + o) * 88 + k];
    xhat[o * 88 + k] = acc;
}

__global__ void gather_nodes_k(const float* __restrict__ p5, float* __restrict__ nodes)
{
    int idx = blockIdx.x * blockDim.x + threadIdx.x;
    if (idx >= TMN * 256) return;
    int d = idx % 256;
    int n = idx / 256;
    int t = n % 16, m = n / 16;
    nodes[idx] = p5[((size_t)t * 256 + d) * 88 + m];
}

__global__ __launch_bounds__(256)
void rbgemm_k(const float* __restrict__ A, const float* __restrict__ B,
              const float* __restrict__ bias, float* __restrict__ C,
              int M, int N, int K, int flags)
{
    __shared__ float As[16][65];
    __shared__ float Bs[16][64];
    int tid = threadIdx.x;
    int tx = tid & 15;
    int ty = tid >> 4;
    int m0 = blockIdx.y * 64;
    int n0 = blockIdx.x * 64;

    float acc[4][4] = {};

    for (int k0 = 0; k0 < K; k0 += 16) {
        #pragma unroll
        for (int i = 0; i < 4; i++) {
            int e  = tid + i * 256;
            int kk = e & 15;
            int mm = e >> 4;
            int gm = m0 + mm, gk = k0 + kk;
            As[kk][mm] = (gm < M && gk < K) ? A[(size_t)gm * K + gk] : 0.f;
        }
        #pragma unroll
        for (int i = 0; i < 4; i++) {
            int nn = tid & 63;
            int kk = (tid >> 6) + i * 4;
            int gk = k0 + kk, gn = n0 + nn;
            Bs[kk][nn] = (gk < K && gn < N) ? B[(size_t)gk * N + gn] : 0.f;
        }
        __syncthreads();
        #pragma unroll
        for (int kk = 0; kk < 16; kk++) {
            float ra[4], rb[4];
            #pragma unroll
            for (int i = 0; i < 4; i++) ra[i] = As[kk][ty * 4 + i];
            #pragma unroll
            for (int j = 0; j < 4; j++) rb[j] = Bs[kk][tx * 4 + j];
            #pragma unroll
            for (int i = 0; i < 4; i++)
                #pragma unroll
                for (int j = 0; j < 4; j++)
                    acc[i][j] += ra[i] * rb[j];
        }
        __syncthreads();
    }

    #pragma unroll
    for (int i = 0; i < 4; i++) {
        int gm = m0 + ty * 4 + i;
        if (gm >= M) continue;
        #pragma unroll
        for (int j = 0; j < 4; j++) {
            int gn = n0 + tx * 4 + j;
            if (gn >= N) continue;
            float v = acc[i][j];
            if (flags & 1) v += bias[gm];
            if (flags & 2) v += bias[gn];
            if (flags & 4) v = v >= 0.f ? v : 0.01f * v;
            C[(size_t)gm * N + gn] = v;
        }
    }
}

__global__ void a1_reduce_k(const float* __restrict__ Y, float* __restrict__ S, int F)
{
    int f = blockIdx.x * blockDim.x + threadIdx.x;
    int t = blockIdx.y;
    if (f >= F) return;
    float s = 0.f;
    for (int m = 0; m < 88; m++) s += Y[(size_t)(m * 16 + t) * F + f];
    S[t * F + f] = s;
}

__global__ void a1_apply_k(const float* __restrict__ Y, const float* __restrict__ S,
                           const float* __restrict__ bias, float* __restrict__ h, int F)
{
    int idx = blockIdx.x * blockDim.x + threadIdx.x;
    if (idx >= TMN * F) return;
    int f = idx % F;
    int n = idx / F;
    int t = n % 16;
    float val = S[t * F + f] + bias[f];
    if (t == 0) val -= Y[idx];
    h[idx] = val >= 0.f ? val : 0.01f * val;
}

__global__ void v1_k(const float* __restrict__ h2, const float* __restrict__ xhat,
                     float* __restrict__ V1, float* __restrict__ V1t, float* __restrict__ Vx)
{
    int idx = blockIdx.x * blockDim.x + threadIdx.x;
    if (idx >= 256 * 88) return;
    int d = idx % 256;
    int m = idx / 256;
    float mx = -INFINITY;
    #pragma unroll
    for (int t = 0; t < 16; t++) mx = fmaxf(mx, h2[(size_t)(m * 16 + t) * 256 + d]);
    V1[d * 88 + m] = mx;
    V1t[m * 256 + d] = mx;
    Vx[d * 88 + m] = mx + xhat[d * 88 + m];
}

__global__ void attn_k(const float* __restrict__ G, const float* __restrict__ Hh,
                       float* __restrict__ A2)
{
    __shared__ float red[128];
    int j = blockIdx.x;
    int i = threadIdx.x;
    float s = 0.f;
    if (i < 88) {
        for (int d = 0; d < 256; d++) s += Hh[d * 88 + j] * G[d * 88 + i];
    }
    red[i] = (i < 88) ? s : -INFINITY;
    __syncthreads();
    for (int st = 64; st > 0; st >>= 1) {
        if (i < st) red[i] = fmaxf(red[i], red[i + st]);
        __syncthreads();
    }
    float mx = red[0];
    __syncthreads();
    float e = (i < 88) ? expf(s - mx) : 0.f;
    red[i] = e;
    __syncthreads();
    for (int st = 64; st > 0; st >>= 1) {
        if (i < st) red[i] += red[i + st];
        __syncthreads();
    }
    float sum = red[0];
    if (i < 88) A2[j * 88 + i] = e / sum;
}

__global__ void final_dot_k(const float* __restrict__ Xf, const float* __restrict__ V2t,
                            float* __restrict__ out)
{
    __shared__ float red[256];
    float acc = 0.f;
    for (int e = threadIdx.x; e < 256 * 88; e += 256) {
        int d = e / 88, m = e % 88;
        acc += Xf[e] * V2t[m * 256 + d];
    }
    red[threadIdx.x] = acc;
    __syncthreads();
    for (int st = 128; st > 0; st >>= 1) {
        if (threadIdx.x < st) red[threadIdx.x] += red[threadIdx.x + st];
        __syncthreads();
    }
    if (threadIdx.x == 0) out[0] = red[0];
}

// ---------------- host ----------------
static float* symaddr(const void* s)
{
    void* p = nullptr;
    cudaGetSymbolAddress(&p, s);
    return (float*)p;
}
static __nv_bfloat16* symaddr_bf(const void* s)
{
    void* p = nullptr;
    cudaGetSymbolAddress(&p, s);
    return (__nv_bfloat16*)p;
}

extern "C" void kernel_launch(void* const* d_in, const int* in_sizes, int n_in,
                              void* d_out, int out_size)
{
    const float* search    = (const float*)d_in[0];
    const float* exemplars = (const float*)d_in[1];
    const float* aw1 = (const float*)d_in[2];  const float* ab1 = (const float*)d_in[3];
    const float* aw2 = (const float*)d_in[4];  const float* ab2 = (const float*)d_in[5];
    const float* aw3 = (const float*)d_in[6];  const float* ab3 = (const float*)d_in[7];
    const float* aw4 = (const float*)d_in[8];  const float* ab4 = (const float*)d_in[9];
    const float* aw5 = (const float*)d_in[10]; const float* ab5 = (const float*)d_in[11];
    const float* wcd = (const float*)d_in[12]; const float* bcd = (const float*)d_in[13];
    const float* wt  = (const float*)d_in[14]; const float* bt  = (const float*)d_in[15];
    const float* ws1 = (const float*)d_in[16]; const float* bs1 = (const float*)d_in[17];
    const float* ws2 = (const float*)d_in[18]; const float* bs2 = (const float*)d_in[19];
    const float* wg  = (const float*)d_in[20]; const float* bg  = (const float*)d_in[21];
    const float* wh  = (const float*)d_in[22]; const float* bh  = (const float*)d_in[23];
    const float* wc1 = (const float*)d_in[24]; const float* bc1 = (const float*)d_in[25];
    const float* wc2 = (const float*)d_in[26]; const float* bc2 = (const float*)d_in[27];

    float* p_in  = symaddr(g_in);
    float* p_c1  = symaddr(g_c1);
    float* p_p1  = symaddr(g_p1);
    float* p_c2  = symaddr(g_c2);
    float* p_p2  = symaddr(g_p2);
    float* p_c3  = symaddr(g_c3);
    float* p_c4  = symaddr(g_c4);
    float* p_c5  = symaddr(g_c5);
    float* p_p5  = symaddr(g_p5);
    float* p_xc  = symaddr(g_xc);
    float* p_v   = symaddr(g_v);
    float* p_xh  = symaddr(g_xhat);
    float* p_nd  = symaddr(g_nodes);
    float* p_Y1  = symaddr(g_Y1);
    float* p_S   = symaddr(g_S);
    float* p_h1  = symaddr(g_h1);
    float* p_Y2  = symaddr(g_Y2);
    float* p_h2  = symaddr(g_h2);
    float* p_V1  = symaddr(g_V1);
    float* p_V1t = symaddr(g_V1t);
    float* p_Vx  = symaddr(g_Vx);
    float* p_G   = symaddr(g_G);
    float* p_Hh  = symaddr(g_Hh);
    float* p_A2  = symaddr(g_A2);
    float* p_xw  = symaddr(g_xw);
    float* p_c1m = symaddr(g_c1m);
    float* p_cw  = symaddr(g_cw);
    float* p_V2t = symaddr(g_V2t);
    __nv_bfloat16* pAhi = symaddr_bf(g_Ahi);
    __nv_bfloat16* pAlo = symaddr_bf(g_Alo);
    __nv_bfloat16* pBhi = symaddr_bf(g_Bhi);
    __nv_bfloat16* pBlo = symaddr_bf(g_Blo);

    // zero padded buffers (borders must be 0 every replay)
    cudaMemsetAsync(p_in, 0, sizeof(float) * ((size_t)N_IMG * 3 * H0P * W0P + TAILPAD), 0);
    cudaMemsetAsync(p_p1, 0, sizeof(float) * ((size_t)N_IMG * C1o * P1HP * P1WP + TAILPAD), 0);
    cudaMemsetAsync(p_p2, 0, sizeof(float) * ((size_t)N_IMG * C2o * P2HP * P2WP + TAILPAD), 0);
    cudaMemsetAsync(p_c3, 0, sizeof(float) * ((size_t)N_IMG * C3o * P2HP * P2WP + TAILPAD), 0);
    cudaMemsetAsync(p_c4, 0, sizeof(float) * ((size_t)N_IMG * C4o * P2HP * P2WP + TAILPAD), 0);

    // assemble padded input batch
    {
        int tot = 16 * 3 * H0 * W0;
        pad_copy_k<<<(tot + 127) / 128, 128>>>(exemplars, p_in, 16, 0);
        tot = 3 * H0 * W0;
        pad_copy_k<<<(tot + 127) / 128, 128>>>(search, p_in, 1, 16);
    }

    // ---- conv1 (scalar) + pool1 ----
    {
        int wq = (W1 + 3) / 4, sp = H1 * wq;
        conv4x4_k<3, 11, 4, 3><<<dim3((sp + 127) / 128, N_IMG * (C1o / 4)), 128>>>(
            p_in, aw1, ab1, p_c1, C1o, H0P, W0P, H1, W1, H1, W1, 0);
    }
    {
        int tot = N_IMG * C1o * P1H * P1W;
        maxpool_k<<<(tot + 127) / 128, 128>>>(p_c1, p_p1, N_IMG * C1o, H1, W1, P1H, P1W, P1HP, P1WP, 2);
    }

    // ---- conv2 (tensor GEMM): Cout=192, K=1600, Npix=17*47*35 ----
    {
        const int K = 64 * 25, NP = N_IMG * H2 * W2;
        wsplit_k<<<(C2o * K + 255) / 256, 256>>>(aw2, pAhi, pAlo, C2o * K);
        long long tot = (long long)NP * K;
        im2col_k<<<(unsigned)((tot + 255) / 256), 256>>>(p_p1, pBhi, pBlo, 64, 5, P1HP, P1WP, H2, W2, K, NP);
        mmaconv_k<<<dim3((NP + 63) / 64, 2), 256>>>(
            pAhi, pAlo, pBhi, pBlo, ab2, p_c2, C2o, NP, K, H2, W2, H2, W2, 0);
    }
    {
        int tot = N_IMG * C2o * P2H * P2W;
        maxpool_k<<<(tot + 127) / 128, 128>>>(p_c2, p_p2, N_IMG * C2o, H2, W2, P2H, P2W, P2HP, P2WP, 1);
    }

    // ---- conv3: Cout=384, K=1728 ----
    {
        const int K = 192 * 9, NP = N_IMG * P2H * P2W;
        wsplit_k<<<(C3o * K + 255) / 256, 256>>>(aw3, pAhi, pAlo, C3o * K);
        long long tot = (long long)NP * K;
        im2col_k<<<(unsigned)((tot + 255) / 256), 256>>>(p_p2, pBhi, pBlo, 192, 3, P2HP, P2WP, P2H, P2W, K, NP);
        mmaconv_k<<<dim3((NP + 63) / 64, 3), 256>>>(
            pAhi, pAlo, pBhi, pBlo, ab3, p_c3, C3o, NP, K, P2H, P2W, P2HP, P2WP, 1);
    }

    // ---- conv4: Cout=256, K=3456 ----
    {
        const int K = 384 * 9, NP = N_IMG * P2H * P2W;
        wsplit_k<<<(C4o * K + 255) / 256, 256>>>(aw4, pAhi, pAlo, C4o * K);
        long long tot = (long long)NP * K;
        im2col_k<<<(unsigned)((tot + 255) / 256), 256>>>(p_c3, pBhi, pBlo, 384, 3, P2HP, P2WP, P2H, P2W, K, NP);
        mmaconv_k<<<dim3((NP + 63) / 64, 2), 256>>>(
            pAhi, pAlo, pBhi, pBlo, ab4, p_c4, C4o, NP, K, P2H, P2W, P2HP, P2WP, 1);
    }

    // ---- conv5: Cout=256, K=2304, out unpadded ----
    {
        const int K = 256 * 9, NP = N_IMG * P2H * P2W;
        wsplit_k<<<(C5o * K + 255) / 256, 256>>>(aw5, pAhi, pAlo, C5o * K);
        long long tot = (long long)NP * K;
        im2col_k<<<(unsigned)((tot + 255) / 256), 256>>>(p_c4, pBhi, pBlo, 256, 3, P2HP, P2WP, P2H, P2W, K, NP);
        mmaconv_k<<<dim3((NP + 63) / 64, 2), 256>>>(
            pAhi, pAlo, pBhi, pBlo, ab5, p_c5, C5o, NP, K, H5, W5, H5, W5, 0);
    }
    {
        int tot = N_IMG * C5o * P5H * P5W;
        maxpool_k<<<(tot + 127) / 128, 128>>>(p_c5, p_p5, N_IMG * C5o, H5, W5, P5H, P5W, P5H, P5W, 0);
    }

    const float* Xf = p_p5 + (size_t)16 * 256 * 88;

    // ---- conv_deconv branch ----
    cd_conv_k<<<88, 256>>>(Xf, wcd, bcd, p_xc);
    cd_max_k<<<1, 256>>>(p_xc, p_v);
    xhat_k<<<256, 88>>>(p_v, wt, bt, p_xh);

    // ---- spatiotemporal GCN ----
    gather_nodes_k<<<(TMN * 256 + 127) / 128, 128>>>(p_p5, p_nd);
    rbgemm_k<<<dim3(512 / 64, TMN / 64), 256>>>(p_nd, ws1, nullptr, p_Y1, TMN, 512, 256, 0);
    a1_reduce_k<<<dim3(4, 16), 128>>>(p_Y1, p_S, 512);
    a1_apply_k<<<(TMN * 512 + 255) / 256, 256>>>(p_Y1, p_S, bs1, p_h1, 512);
    rbgemm_k<<<dim3(256 / 64, TMN / 64), 256>>>(p_h1, ws2, nullptr, p_Y2, TMN, 256, 512, 0);
    a1_reduce_k<<<dim3(2, 16), 128>>>(p_Y2, p_S, 256);
    a1_apply_k<<<(TMN * 256 + 255) / 256, 256>>>(p_Y2, p_S, bs2, p_h2, 256);
    v1_k<<<(256 * 88 + 255) / 256, 256>>>(p_h2, p_xh, p_V1, p_V1t, p_Vx);

    // ---- dynamic cross-track graph ----
    rbgemm_k<<<dim3((88 + 63) / 64, 256 / 64), 256>>>(wg, p_Vx, bg, p_G, 256, 88, 256, 1);
    rbgemm_k<<<dim3((88 + 63) / 64, 256 / 64), 256>>>(wh, p_Vx, bh, p_Hh, 256, 88, 256, 1);
    attn_k<<<88, 128>>>(p_G, p_Hh, p_A2);

    // ---- ct GCN ----
    rbgemm_k<<<dim3(384 / 64, (88 + 63) / 64), 256>>>(p_V1t, wc1, nullptr, p_xw, 88, 384, 256, 0);
    rbgemm_k<<<dim3(384 / 64, (88 + 63) / 64), 256>>>(p_A2, p_xw, bc1, p_c1m, 88, 384, 88, 2 | 4);
    rbgemm_k<<<dim3(256 / 64, (88 + 63) / 64), 256>>>(p_c1m, wc2, nullptr, p_cw, 88, 256, 384, 0);
    rbgemm_k<<<dim3(256 / 64, (88 + 63) / 64), 256>>>(p_A2, p_cw, bc2, p_V2t, 88, 256, 88, 2 | 4);

    // ---- final correlation ----
    final_dot_k<<<1, 256>>>(Xf, p_V2t, (float*)d_out);
}

// round 7
// speedup vs baseline: 1.7783x; 1.4515x over previous
#include <cuda_runtime.h>
#include <cuda_bf16.h>
#include <cstdint>
#include <math.h>

// ---------------- dimensions ----------------
#define N_IMG 17
#define H0 383
#define W0 287
#define H0P 387
#define W0P 291
#define C1o 64
#define H1 95
#define W1 71
#define P1H 47
#define P1W 35
#define P1HP 51
#define P1WP 39
#define C2o 192
#define H2 47
#define W2 35
#define P2H 23
#define P2W 17
#define P2HP 25
#define P2WP 19
#define C3o 384
#define C4o 256
#define C5o 256
#define H5 23
#define W5 17
#define P5H 11
#define P5W 8
#define MM 88
#define TT 16
#define TMN 1408
#define TAILPAD 4096

// ---------------- scratch (device globals; no allocation) ----------------
__device__ float g_in [N_IMG*3*H0P*W0P + TAILPAD];
__device__ float g_c1 [N_IMG*C1o*H1*W1];
__device__ float g_p1 [N_IMG*C1o*P1HP*P1WP + TAILPAD];
__device__ float g_c2 [N_IMG*C2o*H2*W2];
__device__ float g_p2 [N_IMG*C2o*P2HP*P2WP + TAILPAD];
__device__ float g_c3 [N_IMG*C3o*P2HP*P2WP + TAILPAD];
__device__ float g_c4 [N_IMG*C4o*P2HP*P2WP + TAILPAD];
__device__ float g_c5 [N_IMG*C5o*H5*W5];
__device__ float g_p5 [N_IMG*C5o*MM];
__device__ float g_xc [256*88];
__device__ float g_v  [256];
__device__ float g_xhat[256*88];
__device__ float g_nodes[TMN*256];
__device__ float g_Y1 [TMN*512];
__device__ float g_S  [16*512];
__device__ float g_h1 [TMN*512];
__device__ float g_Y2 [TMN*256];
__device__ float g_h2 [TMN*256];
__device__ float g_V1 [256*88];
__device__ float g_V1t[88*256];
__device__ float g_Vx [256*88];
__device__ float g_G  [256*88];
__device__ float g_Hh [256*88];
__device__ float g_A2 [88*88];
__device__ float g_xw [88*384];
__device__ float g_c1m[88*384];
__device__ float g_cw [88*256];
__device__ float g_V2t[88*256];

// bf16 split matrices for tensor-core conv GEMMs
__device__ __nv_bfloat16 g_Ahi[384*3456];
__device__ __nv_bfloat16 g_Alo[384*3456];
__device__ __nv_bfloat16 g_Bhi[44800000];
__device__ __nv_bfloat16 g_Blo[44800000];

// ---------------- mma / cp.async helpers (baseline PTX, sm_80+) ----------------
__device__ __forceinline__ uint32_t smem_u32(const void* p)
{
    uint32_t a;
    asm("{ .reg .u64 t; cvta.to.shared.u64 t, %1; cvt.u32.u64 %0, t; }" : "=r"(a) : "l"(p));
    return a;
}
__device__ __forceinline__ void ldsm_x4(uint32_t& r0, uint32_t& r1, uint32_t& r2, uint32_t& r3,
                                        uint32_t addr)
{
    asm volatile("ldmatrix.sync.aligned.m8n8.x4.shared.b16 {%0,%1,%2,%3}, [%4];"
                 : "=r"(r0), "=r"(r1), "=r"(r2), "=r"(r3) : "r"(addr));
}
__device__ __forceinline__ void mma16816(float* d, const uint32_t* a, uint32_t b0, uint32_t b1)
{
    asm volatile("mma.sync.aligned.m16n8k16.row.col.f32.bf16.bf16.f32 "
                 "{%0,%1,%2,%3}, {%4,%5,%6,%7}, {%8,%9}, {%0,%1,%2,%3};"
                 : "+f"(d[0]), "+f"(d[1]), "+f"(d[2]), "+f"(d[3])
                 : "r"(a[0]), "r"(a[1]), "r"(a[2]), "r"(a[3]), "r"(b0), "r"(b1));
}
__device__ __forceinline__ void cp16(uint32_t dst, const void* src, bool pred)
{
    int sz = pred ? 16 : 0;
    asm volatile("cp.async.cg.shared.global [%0], [%1], 16, %2;"
                 :: "r"(dst), "l"(src), "r"(sz));
}
#define CP_COMMIT() asm volatile("cp.async.commit_group;" ::: "memory")
#define CP_WAIT(n)  asm volatile("cp.async.wait_group %0;" :: "n"(n) : "memory")

// ---------------- prep kernels ----------------
// weight split with K padding: A[m, k<Kreal] from w, else 0
__global__ void wsplit_pad_k(const float* __restrict__ w, __nv_bfloat16* __restrict__ hi,
                             __nv_bfloat16* __restrict__ lo, int M, int Kreal, int KPAD)
{
    int i = blockIdx.x * blockDim.x + threadIdx.x;
    if (i >= M * KPAD) return;
    int m = i / KPAD, k = i - m * KPAD;
    float x = (k < Kreal) ? w[(size_t)m * Kreal + k] : 0.f;
    __nv_bfloat16 h = __float2bfloat16_rn(x);
    hi[i] = h;
    lo[i] = __float2bfloat16_rn(x - __bfloat162float(h));
}

// fully templated im2col + bf16 split: all divisors compile-time
template<int CIN, int KD, int S, int HinP, int WinP, int Hout, int Wout, int KPAD>
__global__ void im2col_t(const float* __restrict__ in,
                         __nv_bfloat16* __restrict__ bhi, __nv_bfloat16* __restrict__ blo)
{
    constexpr int KK = KD * KD;
    constexpr int KREAL = CIN * KK;
    constexpr int HW = Hout * Wout;
    constexpr int NPIX = N_IMG * HW;
    int idx = blockIdx.x * blockDim.x + threadIdx.x;
    if (idx >= NPIX * KPAD) return;
    int p = idx / KPAD;
    int k = idx - p * KPAD;
    float x = 0.f;
    if (k < KREAL) {
        int ci = k / KK;
        int r  = k - ci * KK;
        int kh = r / KD;
        int kw = r - kh * KD;
        int img = p / HW;
        int rr  = p - img * HW;
        int oh  = rr / Wout;
        int ow  = rr - oh * Wout;
        x = in[((size_t)(img * CIN + ci) * HinP + oh * S + kh) * WinP + ow * S + kw];
    }
    __nv_bfloat16 h = __float2bfloat16_rn(x);
    bhi[idx] = h;
    blo[idx] = __float2bfloat16_rn(x - __bfloat162float(h));
}

// ---------------- tensor-core conv GEMM, cp.async double-buffered ----------------
#define ASTR 72
#define SZ_A (128 * ASTR * 2)      // bytes per A stage
#define SZ_B (64 * ASTR * 2)       // bytes per B stage
#define SMEM_GEMM (2 * SZ_A + 2 * SZ_B)

__global__ void __launch_bounds__(256)
mmaconv_k(const __nv_bfloat16* __restrict__ Ahi, const __nv_bfloat16* __restrict__ Alo,
          const __nv_bfloat16* __restrict__ Bhi, const __nv_bfloat16* __restrict__ Blo,
          const float* __restrict__ bias, float* __restrict__ out,
          int M, int Npix, int K, int Hout, int Wout,
          int HoP, int WoP, int opad)
{
    extern __shared__ char smem[];
    uint32_t sb = smem_u32(smem);
    // stage offsets: A0, A1, B0, B1
    uint32_t aOff[2] = { sb, sb + SZ_A };
    uint32_t bOff[2] = { sb + 2 * SZ_A, sb + 2 * SZ_A + SZ_B };

    int tid  = threadIdx.x;
    int lane = tid & 31;
    int wid  = tid >> 5;
    int wm   = wid & 3;
    int wn   = wid >> 2;

    int m0 = blockIdx.y * 128;
    int n0 = blockIdx.x * 64;

    float d[2][4][4];
    #pragma unroll
    for (int i = 0; i < 2; i++)
        #pragma unroll
        for (int j = 0; j < 4; j++)
            #pragma unroll
            for (int r = 0; r < 4; r++) d[i][j][r] = 0.f;

    int aj = lane >> 3, ar = lane & 7;
    uint32_t aAddrOff = (uint32_t)(((aj & 1) * 8 + ar) * ASTR + (aj >> 1) * 8) * 2;
    uint32_t bAddrOff = (uint32_t)(((aj >> 1) * 8 + ar) * ASTR + (aj & 1) * 8) * 2;

    int per = K >> 6;
    int itK = 3 * per;

    // per-thread load coordinates
    int arow[4], aq[4];
    #pragma unroll
    for (int j = 0; j < 4; j++) {
        int i = tid + j * 256;
        arow[j] = i >> 3; aq[j] = i & 7;
    }
    int brow[2], bq[2];
    #pragma unroll
    for (int j = 0; j < 2; j++) {
        int i = tid + j * 256;
        brow[j] = i >> 3; bq[j] = i & 7;
    }

    // stage loader
    auto load_stage = [&](int st, int it) {
        int seg = it / per;
        int kof = (it - seg * per) << 6;
        const __nv_bfloat16* As = (seg < 2) ? Ahi : Alo;
        const __nv_bfloat16* Bs = (seg == 1) ? Blo : Bhi;
        #pragma unroll
        for (int j = 0; j < 4; j++) {
            uint32_t dst = aOff[st] + (uint32_t)(arow[j] * ASTR + aq[j] * 8) * 2;
            cp16(dst, As + (size_t)(m0 + arow[j]) * K + kof + aq[j] * 8, m0 + arow[j] < M);
        }
        #pragma unroll
        for (int j = 0; j < 2; j++) {
            uint32_t dst = bOff[st] + (uint32_t)(brow[j] * ASTR + bq[j] * 8) * 2;
            cp16(dst, Bs + (size_t)(n0 + brow[j]) * K + kof + bq[j] * 8, n0 + brow[j] < Npix);
        }
        CP_COMMIT();
    };

    load_stage(0, 0);

    for (int it = 0; it < itK; it++) {
        int st = it & 1;
        if (it + 1 < itK) {
            load_stage(st ^ 1, it + 1);
            CP_WAIT(1);
        } else {
            CP_WAIT(0);
        }
        __syncthreads();

        #pragma unroll
        for (int kk = 0; kk < 4; kk++) {
            uint32_t a[2][4];
            #pragma unroll
            for (int mi = 0; mi < 2; mi++) {
                uint32_t ad = aOff[st] + aAddrOff
                            + (uint32_t)((wm * 32 + mi * 16) * ASTR + kk * 16) * 2;
                ldsm_x4(a[mi][0], a[mi][1], a[mi][2], a[mi][3], ad);
            }
            uint32_t b[4][2];
            #pragma unroll
            for (int q = 0; q < 2; q++) {
                uint32_t bd = bOff[st] + bAddrOff
                            + (uint32_t)((wn * 32 + q * 16) * ASTR + kk * 16) * 2;
                uint32_t r0, r1, r2, r3;
                ldsm_x4(r0, r1, r2, r3, bd);
                b[q * 2][0] = r0;  b[q * 2][1] = r1;
                b[q * 2 + 1][0] = r2;  b[q * 2 + 1][1] = r3;
            }
            #pragma unroll
            for (int mi = 0; mi < 2; mi++)
                #pragma unroll
                for (int nj = 0; nj < 4; nj++)
                    mma16816(d[mi][nj], a[mi], b[nj][0], b[nj][1]);
        }
        __syncthreads();
    }

    // epilogue: bias + ReLU + NCHW scatter
    int HW = Hout * Wout;
    #pragma unroll
    for (int mi = 0; mi < 2; mi++) {
        #pragma unroll
        for (int r2 = 0; r2 < 2; r2++) {
            int co = m0 + wm * 32 + mi * 16 + (lane >> 2) + r2 * 8;
            if (co >= M) continue;
            float bv = bias[co];
            #pragma unroll
            for (int nj = 0; nj < 4; nj++) {
                #pragma unroll
                for (int c = 0; c < 2; c++) {
                    int p = n0 + wn * 32 + nj * 8 + (lane & 3) * 2 + c;
                    if (p >= Npix) continue;
                    float v = d[mi][nj][r2 * 2 + c] + bv;
                    int img = p / HW;
                    int rr  = p - img * HW;
                    int oh  = rr / Wout;
                    int ow  = rr - oh * Wout;
                    out[((size_t)(img * M + co) * HoP + oh + opad) * WoP + ow + opad]
                        = fmaxf(v, 0.f);
                }
            }
        }
    }
}

// ---------------- scalar kernels (rest of network) ----------------

__global__ void pad_copy_k(const float* __restrict__ src, float* __restrict__ dst,
                           int nimg, int boff)
{
    int idx = blockIdx.x * blockDim.x + threadIdx.x;
    int total = nimg * 3 * H0 * W0;
    if (idx >= total) return;
    int w = idx % W0; int t = idx / W0;
    int h = t % H0;   t /= H0;
    int c = t % 3;    int n = t / 3;
    dst[(((size_t)(boff + n) * 3 + c) * H0P + h + 2) * W0P + (w + 2)] = src[idx];
}

__global__ void maxpool_k(const float* __restrict__ in, float* __restrict__ out,
                          int NC, int Hin, int Win, int Ho, int Wo,
                          int HoP, int WoP, int opad)
{
    int idx = blockIdx.x * blockDim.x + threadIdx.x;
    int total = NC * Ho * Wo;
    if (idx >= total) return;
    int ow = idx % Wo; int t = idx / Wo;
    int oh = t % Ho;   int nc = t / Ho;
    const float* ip = in + ((size_t)nc * Hin + oh * 2) * Win + ow * 2;
    float m = -INFINITY;
    #pragma unroll
    for (int kh = 0; kh < 3; kh++)
        #pragma unroll
        for (int kw = 0; kw < 3; kw++)
            m = fmaxf(m, ip[kh * Win + kw]);
    out[((size_t)nc * HoP + oh + opad) * WoP + ow + opad] = m;
}

__global__ void cd_conv_k(const float* __restrict__ Xf, const float* __restrict__ wcd,
                          const float* __restrict__ bcd, float* __restrict__ xc)
{
    int p = blockIdx.x;
    int o = threadIdx.x;
    float acc = bcd[o];
    for (int i = 0; i < 256; i++) {
        const float* wr = wcd + (o * 256 + i) * 3;
        const float* xr = Xf + i * 88;
        if (p > 0)  acc += xr[p - 1] * wr[0];
        acc += xr[p] * wr[1];
        if (p < 87) acc += xr[p + 1] * wr[2];
    }
    xc[o * 88 + p] = acc;
}

__global__ void cd_max_k(const float* __restrict__ xc, float* __restrict__ v)
{
    int o = threadIdx.x;
    float m = -INFINITY;
    for (int p = 0; p < 88; p++) m = fmaxf(m, xc[o * 88 + p]);
    v[o] = m;
}

__global__ void xhat_k(const float* __restrict__ v, const float* __restrict__ wt,
                       const float* __restrict__ bt, float* __restrict__ xhat)
{
    __shared__ float sv[256];
    int o = blockIdx.x;
    int k = threadIdx.x;
    for (int i = threadIdx.x; i < 256; i += blockDim.x) sv[i] = v[i];
    __syncthreads();
    float acc = bt[o];
    for (int i = 0; i < 256; i++)
        acc += sv[i] * wt[((size_t)i * 256 + o) * 88 + k];
    xhat[o * 88 + k] = acc;
}

__global__ void gather_nodes_k(const float* __restrict__ p5, float* __restrict__ nodes)
{
    int idx = blockIdx.x * blockDim.x + threadIdx.x;
    if (idx >= TMN * 256) return;
    int d = idx % 256;
    int n = idx / 256;
    int t = n % 16, m = n / 16;
    nodes[idx] = p5[((size_t)t * 256 + d) * 88 + m];
}

__global__ __launch_bounds__(256)
void rbgemm_k(const float* __restrict__ A, const float* __restrict__ B,
              const float* __restrict__ bias, float* __restrict__ C,
              int M, int N, int K, int flags)
{
    __shared__ float As[16][65];
    __shared__ float Bs[16][64];
    int tid = threadIdx.x;
    int tx = tid & 15;
    int ty = tid >> 4;
    int m0 = blockIdx.y * 64;
    int n0 = blockIdx.x * 64;

    float acc[4][4] = {};

    for (int k0 = 0; k0 < K; k0 += 16) {
        #pragma unroll
        for (int i = 0; i < 4; i++) {
            int e  = tid + i * 256;
            int kk = e & 15;
            int mm = e >> 4;
            int gm = m0 + mm, gk = k0 + kk;
            As[kk][mm] = (gm < M && gk < K) ? A[(size_t)gm * K + gk] : 0.f;
        }
        #pragma unroll
        for (int i = 0; i < 4; i++) {
            int nn = tid & 63;
            int kk = (tid >> 6) + i * 4;
            int gk = k0 + kk, gn = n0 + nn;
            Bs[kk][nn] = (gk < K && gn < N) ? B[(size_t)gk * N + gn] : 0.f;
        }
        __syncthreads();
        #pragma unroll
        for (int kk = 0; kk < 16; kk++) {
            float ra[4], rb[4];
            #pragma unroll
            for (int i = 0; i < 4; i++) ra[i] = As[kk][ty * 4 + i];
            #pragma unroll
            for (int j = 0; j < 4; j++) rb[j] = Bs[kk][tx * 4 + j];
            #pragma unroll
            for (int i = 0; i < 4; i++)
                #pragma unroll
                for (int j = 0; j < 4; j++)
                    acc[i][j] += ra[i] * rb[j];
        }
        __syncthreads();
    }

    #pragma unroll
    for (int i = 0; i < 4; i++) {
        int gm = m0 + ty * 4 + i;
        if (gm >= M) continue;
        #pragma unroll
        for (int j = 0; j < 4; j++) {
            int gn = n0 + tx * 4 + j;
            if (gn >= N) continue;
            float v = acc[i][j];
            if (flags & 1) v += bias[gm];
            if (flags & 2) v += bias[gn];
            if (flags & 4) v = v >= 0.f ? v : 0.01f * v;
            C[(size_t)gm * N + gn] = v;
        }
    }
}

__global__ void a1_reduce_k(const float* __restrict__ Y, float* __restrict__ S, int F)
{
    int f = blockIdx.x * blockDim.x + threadIdx.x;
    int t = blockIdx.y;
    if (f >= F) return;
    float s = 0.f;
    for (int m = 0; m < 88; m++) s += Y[(size_t)(m * 16 + t) * F + f];
    S[t * F + f] = s;
}

__global__ void a1_apply_k(const float* __restrict__ Y, const float* __restrict__ S,
                           const float* __restrict__ bias, float* __restrict__ h, int F)
{
    int idx = blockIdx.x * blockDim.x + threadIdx.x;
    if (idx >= TMN * F) return;
    int f = idx % F;
    int n = idx / F;
    int t = n % 16;
    float val = S[t * F + f] + bias[f];
    if (t == 0) val -= Y[idx];
    h[idx] = val >= 0.f ? val : 0.01f * val;
}

__global__ void v1_k(const float* __restrict__ h2, const float* __restrict__ xhat,
                     float* __restrict__ V1, float* __restrict__ V1t, float* __restrict__ Vx)
{
    int idx = blockIdx.x * blockDim.x + threadIdx.x;
    if (idx >= 256 * 88) return;
    int d = idx % 256;
    int m = idx / 256;
    float mx = -INFINITY;
    #pragma unroll
    for (int t = 0; t < 16; t++) mx = fmaxf(mx, h2[(size_t)(m * 16 + t) * 256 + d]);
    V1[d * 88 + m] = mx;
    V1t[m * 256 + d] = mx;
    Vx[d * 88 + m] = mx + xhat[d * 88 + m];
}

__global__ void attn_k(const float* __restrict__ G, const float* __restrict__ Hh,
                       float* __restrict__ A2)
{
    __shared__ float red[128];
    int j = blockIdx.x;
    int i = threadIdx.x;
    float s = 0.f;
    if (i < 88) {
        for (int d = 0; d < 256; d++) s += Hh[d * 88 + j] * G[d * 88 + i];
    }
    red[i] = (i < 88) ? s : -INFINITY;
    __syncthreads();
    for (int st = 64; st > 0; st >>= 1) {
        if (i < st) red[i] = fmaxf(red[i], red[i + st]);
        __syncthreads();
    }
    float mx = red[0];
    __syncthreads();
    float e = (i < 88) ? expf(s - mx) : 0.f;
    red[i] = e;
    __syncthreads();
    for (int st = 64; st > 0; st >>= 1) {
        if (i < st) red[i] += red[i + st];
        __syncthreads();
    }
    float sum = red[0];
    if (i < 88) A2[j * 88 + i] = e / sum;
}

__global__ void final_dot_k(const float* __restrict__ Xf, const float* __restrict__ V2t,
                            float* __restrict__ out)
{
    __shared__ float red[256];
    float acc = 0.f;
    for (int e = threadIdx.x; e < 256 * 88; e += 256) {
        int d = e / 88, m = e % 88;
        acc += Xf[e] * V2t[m * 256 + d];
    }
    red[threadIdx.x] = acc;
    __syncthreads();
    for (int st = 128; st > 0; st >>= 1) {
        if (threadIdx.x < st) red[threadIdx.x] += red[threadIdx.x + st];
        __syncthreads();
    }
    if (threadIdx.x == 0) out[0] = red[0];
}

// ---------------- host ----------------
static float* symaddr(const void* s)
{
    void* p = nullptr;
    cudaGetSymbolAddress(&p, s);
    return (float*)p;
}
static __nv_bfloat16* symaddr_bf(const void* s)
{
    void* p = nullptr;
    cudaGetSymbolAddress(&p, s);
    return (__nv_bfloat16*)p;
}

extern "C" void kernel_launch(void* const* d_in, const int* in_sizes, int n_in,
                              void* d_out, int out_size)
{
    const float* search    = (const float*)d_in[0];
    const float* exemplars = (const float*)d_in[1];
    const float* aw1 = (const float*)d_in[2];  const float* ab1 = (const float*)d_in[3];
    const float* aw2 = (const float*)d_in[4];  const float* ab2 = (const float*)d_in[5];
    const float* aw3 = (const float*)d_in[6];  const float* ab3 = (const float*)d_in[7];
    const float* aw4 = (const float*)d_in[8];  const float* ab4 = (const float*)d_in[9];
    const float* aw5 = (const float*)d_in[10]; const float* ab5 = (const float*)d_in[11];
    const float* wcd = (const float*)d_in[12]; const float* bcd = (const float*)d_in[13];
    const float* wt  = (const float*)d_in[14]; const float* bt  = (const float*)d_in[15];
    const float* ws1 = (const float*)d_in[16]; const float* bs1 = (const float*)d_in[17];
    const float* ws2 = (const float*)d_in[18]; const float* bs2 = (const float*)d_in[19];
    const float* wg  = (const float*)d_in[20]; const float* bg  = (const float*)d_in[21];
    const float* wh  = (const float*)d_in[22]; const float* bh  = (const float*)d_in[23];
    const float* wc1 = (const float*)d_in[24]; const float* bc1 = (const float*)d_in[25];
    const float* wc2 = (const float*)d_in[26]; const float* bc2 = (const float*)d_in[27];

    float* p_in  = symaddr(g_in);
    float* p_c1  = symaddr(g_c1);
    float* p_p1  = symaddr(g_p1);
    float* p_c2  = symaddr(g_c2);
    float* p_p2  = symaddr(g_p2);
    float* p_c3  = symaddr(g_c3);
    float* p_c4  = symaddr(g_c4);
    float* p_c5  = symaddr(g_c5);
    float* p_p5  = symaddr(g_p5);
    float* p_xc  = symaddr(g_xc);
    float* p_v   = symaddr(g_v);
    float* p_xh  = symaddr(g_xhat);
    float* p_nd  = symaddr(g_nodes);
    float* p_Y1  = symaddr(g_Y1);
    float* p_S   = symaddr(g_S);
    float* p_h1  = symaddr(g_h1);
    float* p_Y2  = symaddr(g_Y2);
    float* p_h2  = symaddr(g_h2);
    float* p_V1  = symaddr(g_V1);
    float* p_V1t = symaddr(g_V1t);
    float* p_Vx  = symaddr(g_Vx);
    float* p_G   = symaddr(g_G);
    float* p_Hh  = symaddr(g_Hh);
    float* p_A2  = symaddr(g_A2);
    float* p_xw  = symaddr(g_xw);
    float* p_c1m = symaddr(g_c1m);
    float* p_cw  = symaddr(g_cw);
    float* p_V2t = symaddr(g_V2t);
    __nv_bfloat16* pAhi = symaddr_bf(g_Ahi);
    __nv_bfloat16* pAlo = symaddr_bf(g_Alo);
    __nv_bfloat16* pBhi = symaddr_bf(g_Bhi);
    __nv_bfloat16* pBlo = symaddr_bf(g_Blo);

    cudaFuncSetAttribute(mmaconv_k, cudaFuncAttributeMaxDynamicSharedMemorySize, SMEM_GEMM);

    // zero padded buffers (borders must be 0 every replay)
    cudaMemsetAsync(p_in, 0, sizeof(float) * ((size_t)N_IMG * 3 * H0P * W0P + TAILPAD), 0);
    cudaMemsetAsync(p_p1, 0, sizeof(float) * ((size_t)N_IMG * C1o * P1HP * P1WP + TAILPAD), 0);
    cudaMemsetAsync(p_p2, 0, sizeof(float) * ((size_t)N_IMG * C2o * P2HP * P2WP + TAILPAD), 0);
    cudaMemsetAsync(p_c3, 0, sizeof(float) * ((size_t)N_IMG * C3o * P2HP * P2WP + TAILPAD), 0);
    cudaMemsetAsync(p_c4, 0, sizeof(float) * ((size_t)N_IMG * C4o * P2HP * P2WP + TAILPAD), 0);

    // assemble padded input batch
    {
        int tot = 16 * 3 * H0 * W0;
        pad_copy_k<<<(tot + 127) / 128, 128>>>(exemplars, p_in, 16, 0);
        tot = 3 * H0 * W0;
        pad_copy_k<<<(tot + 127) / 128, 128>>>(search, p_in, 1, 16);
    }

    // ---- conv1 (tensor GEMM): M=64, K=363 padded to 384, Npix=17*95*71 ----
    {
        const int KP = 384, NP = N_IMG * H1 * W1;
        wsplit_pad_k<<<(C1o * KP + 255) / 256, 256>>>(aw1, pAhi, pAlo, C1o, 363, KP);
        int tot = NP * KP;
        im2col_t<3, 11, 4, H0P, W0P, H1, W1, 384><<<(tot + 255) / 256, 256>>>(p_in, pBhi, pBlo);
        mmaconv_k<<<dim3((NP + 63) / 64, 1), 256, SMEM_GEMM>>>(
            pAhi, pAlo, pBhi, pBlo, ab1, p_c1, C1o, NP, KP, H1, W1, H1, W1, 0);
    }
    {
        int tot = N_IMG * C1o * P1H * P1W;
        maxpool_k<<<(tot + 127) / 128, 128>>>(p_c1, p_p1, N_IMG * C1o, H1, W1, P1H, P1W, P1HP, P1WP, 2);
    }

    // ---- conv2: Cout=192, K=1600, Npix=17*47*35 ----
    {
        const int KP = 1600, NP = N_IMG * H2 * W2;
        wsplit_pad_k<<<(C2o * KP + 255) / 256, 256>>>(aw2, pAhi, pAlo, C2o, KP, KP);
        int tot = NP * KP;
        im2col_t<64, 5, 1, P1HP, P1WP, H2, W2, 1600><<<(tot + 255) / 256, 256>>>(p_p1, pBhi, pBlo);
        mmaconv_k<<<dim3((NP + 63) / 64, 2), 256, SMEM_GEMM>>>(
            pAhi, pAlo, pBhi, pBlo, ab2, p_c2, C2o, NP, KP, H2, W2, H2, W2, 0);
    }
    {
        int tot = N_IMG * C2o * P2H * P2W;
        maxpool_k<<<(tot + 127) / 128, 128>>>(p_c2, p_p2, N_IMG * C2o, H2, W2, P2H, P2W, P2HP, P2WP, 1);
    }

    // ---- conv3: Cout=384, K=1728 ----
    {
        const int KP = 1728, NP = N_IMG * P2H * P2W;
        wsplit_pad_k<<<(C3o * KP + 255) / 256, 256>>>(aw3, pAhi, pAlo, C3o, KP, KP);
        int tot = NP * KP;
        im2col_t<192, 3, 1, P2HP, P2WP, P2H, P2W, 1728><<<(tot + 255) / 256, 256>>>(p_p2, pBhi, pBlo);
        mmaconv_k<<<dim3((NP + 63) / 64, 3), 256, SMEM_GEMM>>>(
            pAhi, pAlo, pBhi, pBlo, ab3, p_c3, C3o, NP, KP, P2H, P2W, P2HP, P2WP, 1);
    }

    // ---- conv4: Cout=256, K=3456 ----
    {
        const int KP = 3456, NP = N_IMG * P2H * P2W;
        wsplit_pad_k<<<(C4o * KP + 255) / 256, 256>>>(aw4, pAhi, pAlo, C4o, KP, KP);
        int tot = NP * KP;
        im2col_t<384, 3, 1, P2HP, P2WP, P2H, P2W, 3456><<<(tot + 255) / 256, 256>>>(p_c3, pBhi, pBlo);
        mmaconv_k<<<dim3((NP + 63) / 64, 2), 256, SMEM_GEMM>>>(
            pAhi, pAlo, pBhi, pBlo, ab4, p_c4, C4o, NP, KP, P2H, P2W, P2HP, P2WP, 1);
    }

    // ---- conv5: Cout=256, K=2304, out unpadded ----
    {
        const int KP = 2304, NP = N_IMG * P2H * P2W;
        wsplit_pad_k<<<(C5o * KP + 255) / 256, 256>>>(aw5, pAhi, pAlo, C5o, KP, KP);
        int tot = NP * KP;
        im2col_t<256, 3, 1, P2HP, P2WP, P2H, P2W, 2304><<<(tot + 255) / 256, 256>>>(p_c4, pBhi, pBlo);
        mmaconv_k<<<dim3((NP + 63) / 64, 2), 256, SMEM_GEMM>>>(
            pAhi, pAlo, pBhi, pBlo, ab5, p_c5, C5o, NP, KP, H5, W5, H5, W5, 0);
    }
    {
        int tot = N_IMG * C5o * P5H * P5W;
        maxpool_k<<<(tot + 127) / 128, 128>>>(p_c5, p_p5, N_IMG * C5o, H5, W5, P5H, P5W, P5H, P5W, 0);
    }

    const float* Xf = p_p5 + (size_t)16 * 256 * 88;

    // ---- conv_deconv branch ----
    cd_conv_k<<<88, 256>>>(Xf, wcd, bcd, p_xc);
    cd_max_k<<<1, 256>>>(p_xc, p_v);
    xhat_k<<<256, 88>>>(p_v, wt, bt, p_xh);

    // ---- spatiotemporal GCN ----
    gather_nodes_k<<<(TMN * 256 + 127) / 128, 128>>>(p_p5, p_nd);
    rbgemm_k<<<dim3(512 / 64, TMN / 64), 256>>>(p_nd, ws1, nullptr, p_Y1, TMN, 512, 256, 0);
    a1_reduce_k<<<dim3(4, 16), 128>>>(p_Y1, p_S, 512);
    a1_apply_k<<<(TMN * 512 + 255) / 256, 256>>>(p_Y1, p_S, bs1, p_h1, 512);
    rbgemm_k<<<dim3(256 / 64, TMN / 64), 256>>>(p_h1, ws2, nullptr, p_Y2, TMN, 256, 512, 0);
    a1_reduce_k<<<dim3(2, 16), 128>>>(p_Y2, p_S, 256);
    a1_apply_k<<<(TMN * 256 + 255) / 256, 256>>>(p_Y2, p_S, bs2, p_h2, 256);
    v1_k<<<(256 * 88 + 255) / 256, 256>>>(p_h2, p_xh, p_V1, p_V1t, p_Vx);

    // ---- dynamic cross-track graph ----
    rbgemm_k<<<dim3((88 + 63) / 64, 256 / 64), 256>>>(wg, p_Vx, bg, p_G, 256, 88, 256, 1);
    rbgemm_k<<<dim3((88 + 63) / 64, 256 / 64), 256>>>(wh, p_Vx, bh, p_Hh, 256, 88, 256, 1);
    attn_k<<<88, 128>>>(p_G, p_Hh, p_A2);

    // ---- ct GCN ----
    rbgemm_k<<<dim3(384 / 64, (88 + 63) / 64), 256>>>(p_V1t, wc1, nullptr, p_xw, 88, 384, 256, 0);
    rbgemm_k<<<dim3(384 / 64, (88 + 63) / 64), 256>>>(p_A2, p_xw, bc1, p_c1m, 88, 384, 88, 2 | 4);
    rbgemm_k<<<dim3(256 / 64, (88 + 63) / 64), 256>>>(p_c1m, wc2, nullptr, p_cw, 88, 256, 384, 0);
    rbgemm_k<<<dim3(256 / 64, (88 + 63) / 64), 256>>>(p_A2, p_cw, bc2, p_V2t, 88, 256, 88, 2 | 4);

    // ---- final correlation ----
    final_dot_k<<<1, 256>>>(Xf, p_V2t, (float*)d_out);
}

// round 8
// speedup vs baseline: 2.1550x; 1.2119x over previous
#include <cuda_runtime.h>
#include <cuda_bf16.h>
#include <cstdint>
#include <math.h>

// ---------------- dimensions ----------------
#define N_IMG 17
#define H0 383
#define W0 287
#define H0P 387
#define W0P 291
#define C1o 64
#define H1 95
#define W1 71
#define P1H 47
#define P1W 35
#define P1HP 51
#define P1WP 39
#define C2o 192
#define H2 47
#define W2 35
#define P2H 23
#define P2W 17
#define P2HP 25
#define P2WP 19
#define C3o 384
#define C4o 256
#define C5o 256
#define H5 23
#define W5 17
#define P5H 11
#define P5W 8
#define MM 88
#define TT 16
#define TMN 1408
#define TAILPAD 4096

// ---------------- scratch (device globals; no allocation) ----------------
__device__ float g_in [N_IMG*3*H0P*W0P + TAILPAD];
__device__ float g_c1 [N_IMG*C1o*H1*W1];
__device__ float g_p1 [N_IMG*C1o*P1HP*P1WP + TAILPAD];
__device__ float g_c2 [N_IMG*C2o*H2*W2];
__device__ float g_p2 [N_IMG*C2o*P2HP*P2WP + TAILPAD];
__device__ float g_c3 [N_IMG*C3o*P2HP*P2WP + TAILPAD];
__device__ float g_c4 [N_IMG*C4o*P2HP*P2WP + TAILPAD];
__device__ float g_c5 [N_IMG*C5o*H5*W5];
__device__ float g_p5 [N_IMG*C5o*MM];
__device__ float g_xc [256*88];
__device__ float g_v  [256];
__device__ float g_xhat[256*88];
__device__ float g_nodes[TMN*256];
__device__ float g_Y1 [TMN*512];
__device__ float g_S  [16*512];
__device__ float g_h1 [TMN*512];
__device__ float g_Y2 [TMN*256];
__device__ float g_h2 [TMN*256];
__device__ float g_V1 [256*88];
__device__ float g_V1t[88*256];
__device__ float g_Vx [256*88];
__device__ float g_G  [256*88];
__device__ float g_Hh [256*88];
__device__ float g_A2 [88*88];
__device__ float g_xw [88*384];
__device__ float g_c1m[88*384];
__device__ float g_cw [88*256];
__device__ float g_V2t[88*256];

// bf16 split matrices for tensor-core conv GEMMs (also reused as NHWC maps)
__device__ __nv_bfloat16 g_Ahi[384*3456];
__device__ __nv_bfloat16 g_Alo[384*3456];
__device__ __nv_bfloat16 g_Bhi[44800000];
__device__ __nv_bfloat16 g_Blo[44800000];

// ---------------- mma / cp.async helpers (baseline PTX, sm_80+) ----------------
__device__ __forceinline__ uint32_t smem_u32(const void* p)
{
    uint32_t a;
    asm("{ .reg .u64 t; cvta.to.shared.u64 t, %1; cvt.u32.u64 %0, t; }" : "=r"(a) : "l"(p));
    return a;
}
__device__ __forceinline__ void ldsm_x4(uint32_t& r0, uint32_t& r1, uint32_t& r2, uint32_t& r3,
                                        uint32_t addr)
{
    asm volatile("ldmatrix.sync.aligned.m8n8.x4.shared.b16 {%0,%1,%2,%3}, [%4];"
                 : "=r"(r0), "=r"(r1), "=r"(r2), "=r"(r3) : "r"(addr));
}
__device__ __forceinline__ void mma16816(float* d, const uint32_t* a, uint32_t b0, uint32_t b1)
{
    asm volatile("mma.sync.aligned.m16n8k16.row.col.f32.bf16.bf16.f32 "
                 "{%0,%1,%2,%3}, {%4,%5,%6,%7}, {%8,%9}, {%0,%1,%2,%3};"
                 : "+f"(d[0]), "+f"(d[1]), "+f"(d[2]), "+f"(d[3])
                 : "r"(a[0]), "r"(a[1]), "r"(a[2]), "r"(a[3]), "r"(b0), "r"(b1));
}
__device__ __forceinline__ void cp16(uint32_t dst, const void* src, bool pred)
{
    int sz = pred ? 16 : 0;
    asm volatile("cp.async.cg.shared.global [%0], [%1], 16, %2;"
                 :: "r"(dst), "l"(src), "r"(sz));
}
#define CP_COMMIT() asm volatile("cp.async.commit_group;" ::: "memory")
#define CP_WAIT(n)  asm volatile("cp.async.wait_group %0;" :: "n"(n) : "memory")

// ---------------- prep kernels ----------------
// weight split, original k order (ci*KK + kk) with K padding — used by conv1
__global__ void wsplit_pad_k(const float* __restrict__ w, __nv_bfloat16* __restrict__ hi,
                             __nv_bfloat16* __restrict__ lo, int M, int Kreal, int KPAD)
{
    int i = blockIdx.x * blockDim.x + threadIdx.x;
    if (i >= M * KPAD) return;
    int m = i / KPAD, k = i - m * KPAD;
    float x = (k < Kreal) ? w[(size_t)m * Kreal + k] : 0.f;
    __nv_bfloat16 h = __float2bfloat16_rn(x);
    hi[i] = h;
    lo[i] = __float2bfloat16_rn(x - __bfloat162float(h));
}

// weight split + reorder to k = (kh*KD+kw)*CIN + ci (patch-pos outer, channel inner)
__global__ void wsplit_reorder_k(const float* __restrict__ w, __nv_bfloat16* __restrict__ hi,
                                 __nv_bfloat16* __restrict__ lo, int M, int CIN, int KK)
{
    int K = CIN * KK;
    int i = blockIdx.x * blockDim.x + threadIdx.x;
    if (i >= M * K) return;
    int m = i / K, kidx = i - m * K;
    int pos = kidx / CIN, ci = kidx - pos * CIN;
    float x = w[((size_t)m * CIN + ci) * KK + pos];
    __nv_bfloat16 h = __float2bfloat16_rn(x);
    hi[i] = h;
    lo[i] = __float2bfloat16_rn(x - __bfloat162float(h));
}

// NCHW fp32 (padded) -> NHWC bf16 hi/lo via smem transpose. C multiple of 32.
__global__ void nchw2nhwc_k(const float* __restrict__ in,
                            __nv_bfloat16* __restrict__ hi, __nv_bfloat16* __restrict__ lo,
                            int C, int NPIX)
{
    __shared__ float t[32][33];
    int img = blockIdx.z;
    int p0 = blockIdx.x * 32, c0 = blockIdx.y * 32;
    int tx = threadIdx.x, ty = threadIdx.y;
    const float* src = in + (size_t)img * C * NPIX;
    #pragma unroll
    for (int i = 0; i < 4; i++) {
        int c = c0 + ty + i * 8, p = p0 + tx;
        if (p < NPIX) t[ty + i * 8][tx] = src[(size_t)c * NPIX + p];
    }
    __syncthreads();
    #pragma unroll
    for (int i = 0; i < 4; i++) {
        int p = p0 + ty + i * 8, c = c0 + tx;
        if (p < NPIX) {
            float x = t[tx][ty + i * 8];
            __nv_bfloat16 h = __float2bfloat16_rn(x);
            size_t o = ((size_t)img * NPIX + p) * C + c;
            hi[o] = h;
            lo[o] = __float2bfloat16_rn(x - __bfloat162float(h));
        }
    }
}

// explicit im2col for conv1 only (CIN=3, stride 4)
template<int CIN, int KD, int S, int HinP, int WinP, int Hout, int Wout, int KPAD>
__global__ void im2col_t(const float* __restrict__ in,
                         __nv_bfloat16* __restrict__ bhi, __nv_bfloat16* __restrict__ blo)
{
    constexpr int KK = KD * KD;
    constexpr int KREAL = CIN * KK;
    constexpr int HW = Hout * Wout;
    constexpr int NPIX = N_IMG * HW;
    int idx = blockIdx.x * blockDim.x + threadIdx.x;
    if (idx >= NPIX * KPAD) return;
    int p = idx / KPAD;
    int k = idx - p * KPAD;
    float x = 0.f;
    if (k < KREAL) {
        int ci = k / KK;
        int r  = k - ci * KK;
        int kh = r / KD;
        int kw = r - kh * KD;
        int img = p / HW;
        int rr  = p - img * HW;
        int oh  = rr / Wout;
        int ow  = rr - oh * Wout;
        x = in[((size_t)(img * CIN + ci) * HinP + oh * S + kh) * WinP + ow * S + kw];
    }
    __nv_bfloat16 h = __float2bfloat16_rn(x);
    bhi[idx] = h;
    blo[idx] = __float2bfloat16_rn(x - __bfloat162float(h));
}

// ---------------- tensor-core conv GEMMs ----------------
#define ASTR 72

// -------- explicit-B GEMM, 64(M) x 128(N) tile — conv1 only --------
#define A1_SZ (64 * ASTR * 2)
#define B1_SZ (128 * ASTR * 2)
#define SMEM_G1 (2 * A1_SZ + 2 * B1_SZ)
__global__ void __launch_bounds__(256)
mmaconv64_k(const __nv_bfloat16* __restrict__ Ahi, const __nv_bfloat16* __restrict__ Alo,
            const __nv_bfloat16* __restrict__ Bhi, const __nv_bfloat16* __restrict__ Blo,
            const float* __restrict__ bias, float* __restrict__ out,
            int M, int Npix, int K, int Hout, int Wout,
            int HoP, int WoP, int opad)
{
    extern __shared__ char smem[];
    uint32_t sb = smem_u32(smem);
    uint32_t aOff[2] = { sb, sb + A1_SZ };
    uint32_t bOff[2] = { sb + 2 * A1_SZ, sb + 2 * A1_SZ + B1_SZ };

    int tid  = threadIdx.x;
    int lane = tid & 31;
    int wid  = tid >> 5;
    int wm   = wid & 1;          // 2 M warps
    int wn   = wid >> 1;         // 4 N warps

    int m0 = 0;                  // single M tile (M<=64)
    int n0 = blockIdx.x * 128;

    float d[2][4][4];
    #pragma unroll
    for (int i = 0; i < 2; i++)
        #pragma unroll
        for (int j = 0; j < 4; j++)
            #pragma unroll
            for (int r = 0; r < 4; r++) d[i][j][r] = 0.f;

    int aj = lane >> 3, ar = lane & 7;
    uint32_t aAddrOff = (uint32_t)(((aj & 1) * 8 + ar) * ASTR + (aj >> 1) * 8) * 2;
    uint32_t bAddrOff = (uint32_t)(((aj >> 1) * 8 + ar) * ASTR + (aj & 1) * 8) * 2;

    int per = K >> 6;
    int itK = 3 * per;

    int arow[2], aq[2];
    #pragma unroll
    for (int j = 0; j < 2; j++) { int i = tid + j * 256; arow[j] = i >> 3; aq[j] = i & 7; }
    int brow[4], bq[4];
    #pragma unroll
    for (int j = 0; j < 4; j++) { int i = tid + j * 256; brow[j] = i >> 3; bq[j] = i & 7; }

    auto load_stage = [&](int st, int it) {
        int seg = it / per;
        int kof = (it - seg * per) << 6;
        const __nv_bfloat16* As = (seg < 2) ? Ahi : Alo;
        const __nv_bfloat16* Bs = (seg == 1) ? Blo : Bhi;
        #pragma unroll
        for (int j = 0; j < 2; j++) {
            uint32_t dst = aOff[st] + (uint32_t)(arow[j] * ASTR + aq[j] * 8) * 2;
            cp16(dst, As + (size_t)(m0 + arow[j]) * K + kof + aq[j] * 8, m0 + arow[j] < M);
        }
        #pragma unroll
        for (int j = 0; j < 4; j++) {
            uint32_t dst = bOff[st] + (uint32_t)(brow[j] * ASTR + bq[j] * 8) * 2;
            cp16(dst, Bs + (size_t)(n0 + brow[j]) * K + kof + bq[j] * 8, n0 + brow[j] < Npix);
        }
        CP_COMMIT();
    };

    load_stage(0, 0);

    for (int it = 0; it < itK; it++) {
        int st = it & 1;
        if (it + 1 < itK) { load_stage(st ^ 1, it + 1); CP_WAIT(1); }
        else              { CP_WAIT(0); }
        __syncthreads();

        #pragma unroll
        for (int kk = 0; kk < 4; kk++) {
            uint32_t a[2][4];
            #pragma unroll
            for (int mi = 0; mi < 2; mi++) {
                uint32_t ad = aOff[st] + aAddrOff
                            + (uint32_t)((wm * 32 + mi * 16) * ASTR + kk * 16) * 2;
                ldsm_x4(a[mi][0], a[mi][1], a[mi][2], a[mi][3], ad);
            }
            uint32_t b[4][2];
            #pragma unroll
            for (int q = 0; q < 2; q++) {
                uint32_t bd = bOff[st] + bAddrOff
                            + (uint32_t)((wn * 32 + q * 16) * ASTR + kk * 16) * 2;
                uint32_t r0, r1, r2, r3;
                ldsm_x4(r0, r1, r2, r3, bd);
                b[q * 2][0] = r0;  b[q * 2][1] = r1;
                b[q * 2 + 1][0] = r2;  b[q * 2 + 1][1] = r3;
            }
            #pragma unroll
            for (int mi = 0; mi < 2; mi++)
                #pragma unroll
                for (int nj = 0; nj < 4; nj++)
                    mma16816(d[mi][nj], a[mi], b[nj][0], b[nj][1]);
        }
        __syncthreads();
    }

    int HW = Hout * Wout;
    #pragma unroll
    for (int mi = 0; mi < 2; mi++) {
        #pragma unroll
        for (int r2 = 0; r2 < 2; r2++) {
            int co = m0 + wm * 32 + mi * 16 + (lane >> 2) + r2 * 8;
            if (co >= M) continue;
            float bv = bias[co];
            #pragma unroll
            for (int nj = 0; nj < 4; nj++) {
                #pragma unroll
                for (int c = 0; c < 2; c++) {
                    int p = n0 + wn * 32 + nj * 8 + (lane & 3) * 2 + c;
                    if (p >= Npix) continue;
                    float v = d[mi][nj][r2 * 2 + c] + bv;
                    int img = p / HW;
                    int rr  = p - img * HW;
                    int oh  = rr / Wout;
                    int ow  = rr - oh * Wout;
                    out[((size_t)(img * M + co) * HoP + oh + opad) * WoP + ow + opad]
                        = fmaxf(v, 0.f);
                }
            }
        }
    }
}

// -------- implicit-B GEMM, 128(M) x 64(N), B gathered from NHWC map (stride 1) --------
#define A2_SZ (128 * ASTR * 2)
#define B2_SZ (64 * ASTR * 2)
#define SMEM_G2 (2 * A2_SZ + 2 * B2_SZ)
__global__ void __launch_bounds__(256)
mmaconv_imp_k(const __nv_bfloat16* __restrict__ Ahi, const __nv_bfloat16* __restrict__ Alo,
              const __nv_bfloat16* __restrict__ Xhi, const __nv_bfloat16* __restrict__ Xlo,
              const float* __restrict__ bias, float* __restrict__ out,
              int M, int Npix, int K, int CIN, int KD,
              int HinP, int WinP, int Hout, int Wout,
              int HoP, int WoP, int opad)
{
    extern __shared__ char smem[];
    uint32_t sb = smem_u32(smem);
    uint32_t aOff[2] = { sb, sb + A2_SZ };
    uint32_t bOff[2] = { sb + 2 * A2_SZ, sb + 2 * A2_SZ + B2_SZ };

    int tid  = threadIdx.x;
    int lane = tid & 31;
    int wid  = tid >> 5;
    int wm   = wid & 3;
    int wn   = wid >> 2;

    int m0 = blockIdx.y * 128;
    int n0 = blockIdx.x * 64;

    float d[2][4][4];
    #pragma unroll
    for (int i = 0; i < 2; i++)
        #pragma unroll
        for (int j = 0; j < 4; j++)
            #pragma unroll
            for (int r = 0; r < 4; r++) d[i][j][r] = 0.f;

    int aj = lane >> 3, ar = lane & 7;
    uint32_t aAddrOff = (uint32_t)(((aj & 1) * 8 + ar) * ASTR + (aj >> 1) * 8) * 2;
    uint32_t bAddrOff = (uint32_t)(((aj >> 1) * 8 + ar) * ASTR + (aj & 1) * 8) * 2;

    int per = K >> 6;
    int itK = 3 * per;
    int cPer = CIN >> 6;
    int HW = Hout * Wout;

    int arow[4], aq[4];
    #pragma unroll
    for (int j = 0; j < 4; j++) { int i = tid + j * 256; arow[j] = i >> 3; aq[j] = i & 7; }
    int brow[2], bq[2];
    long bbase[2];
    bool bval[2];
    #pragma unroll
    for (int j = 0; j < 2; j++) {
        int i = tid + j * 256;
        brow[j] = i >> 3; bq[j] = i & 7;
        int p = n0 + brow[j];
        bval[j] = p < Npix;
        if (!bval[j]) p = 0;
        int img = p / HW;
        int rr  = p - img * HW;
        int oh  = rr / Wout;
        int ow  = rr - oh * Wout;
        bbase[j] = ((long)(img * HinP + oh) * WinP + ow) * CIN;
    }

    auto load_stage = [&](int st, int it) {
        int seg = it / per;
        int c   = it - seg * per;
        int pos = c / cPer;
        int cioff = (c - pos * cPer) << 6;
        int kh = pos / KD, kw = pos - kh * KD;
        int kofA = c << 6;
        long boff = (long)(kh * WinP + kw) * CIN + cioff;
        const __nv_bfloat16* As = (seg < 2) ? Ahi : Alo;
        const __nv_bfloat16* Bs = (seg == 1) ? Xlo : Xhi;
        #pragma unroll
        for (int j = 0; j < 4; j++) {
            uint32_t dst = aOff[st] + (uint32_t)(arow[j] * ASTR + aq[j] * 8) * 2;
            cp16(dst, As + (size_t)(m0 + arow[j]) * K + kofA + aq[j] * 8, m0 + arow[j] < M);
        }
        #pragma unroll
        for (int j = 0; j < 2; j++) {
            uint32_t dst = bOff[st] + (uint32_t)(brow[j] * ASTR + bq[j] * 8) * 2;
            cp16(dst, Bs + bbase[j] + boff + bq[j] * 8, bval[j]);
        }
        CP_COMMIT();
    };

    load_stage(0, 0);

    for (int it = 0; it < itK; it++) {
        int st = it & 1;
        if (it + 1 < itK) { load_stage(st ^ 1, it + 1); CP_WAIT(1); }
        else              { CP_WAIT(0); }
        __syncthreads();

        #pragma unroll
        for (int kk = 0; kk < 4; kk++) {
            uint32_t a[2][4];
            #pragma unroll
            for (int mi = 0; mi < 2; mi++) {
                uint32_t ad = aOff[st] + aAddrOff
                            + (uint32_t)((wm * 32 + mi * 16) * ASTR + kk * 16) * 2;
                ldsm_x4(a[mi][0], a[mi][1], a[mi][2], a[mi][3], ad);
            }
            uint32_t b[4][2];
            #pragma unroll
            for (int q = 0; q < 2; q++) {
                uint32_t bd = bOff[st] + bAddrOff
                            + (uint32_t)((wn * 32 + q * 16) * ASTR + kk * 16) * 2;
                uint32_t r0, r1, r2, r3;
                ldsm_x4(r0, r1, r2, r3, bd);
                b[q * 2][0] = r0;  b[q * 2][1] = r1;
                b[q * 2 + 1][0] = r2;  b[q * 2 + 1][1] = r3;
            }
            #pragma unroll
            for (int mi = 0; mi < 2; mi++)
                #pragma unroll
                for (int nj = 0; nj < 4; nj++)
                    mma16816(d[mi][nj], a[mi], b[nj][0], b[nj][1]);
        }
        __syncthreads();
    }

    #pragma unroll
    for (int mi = 0; mi < 2; mi++) {
        #pragma unroll
        for (int r2 = 0; r2 < 2; r2++) {
            int co = m0 + wm * 32 + mi * 16 + (lane >> 2) + r2 * 8;
            if (co >= M) continue;
            float bv = bias[co];
            #pragma unroll
            for (int nj = 0; nj < 4; nj++) {
                #pragma unroll
                for (int c = 0; c < 2; c++) {
                    int p = n0 + wn * 32 + nj * 8 + (lane & 3) * 2 + c;
                    if (p >= Npix) continue;
                    float v = d[mi][nj][r2 * 2 + c] + bv;
                    int img = p / HW;
                    int rr  = p - img * HW;
                    int oh  = rr / Wout;
                    int ow  = rr - oh * Wout;
                    out[((size_t)(img * M + co) * HoP + oh + opad) * WoP + ow + opad]
                        = fmaxf(v, 0.f);
                }
            }
        }
    }
}

// ---------------- scalar kernels (rest of network) ----------------

__global__ void pad_copy_k(const float* __restrict__ src, float* __restrict__ dst,
                           int nimg, int boff)
{
    int idx = blockIdx.x * blockDim.x + threadIdx.x;
    int total = nimg * 3 * H0 * W0;
    if (idx >= total) return;
    int w = idx % W0; int t = idx / W0;
    int h = t % H0;   t /= H0;
    int c = t % 3;    int n = t / 3;
    dst[(((size_t)(boff + n) * 3 + c) * H0P + h + 2) * W0P + (w + 2)] = src[idx];
}

__global__ void maxpool_k(const float* __restrict__ in, float* __restrict__ out,
                          int NC, int Hin, int Win, int Ho, int Wo,
                          int HoP, int WoP, int opad)
{
    int idx = blockIdx.x * blockDim.x + threadIdx.x;
    int total = NC * Ho * Wo;
    if (idx >= total) return;
    int ow = idx % Wo; int t = idx / Wo;
    int oh = t % Ho;   int nc = t / Ho;
    const float* ip = in + ((size_t)nc * Hin + oh * 2) * Win + ow * 2;
    float m = -INFINITY;
    #pragma unroll
    for (int kh = 0; kh < 3; kh++)
        #pragma unroll
        for (int kw = 0; kw < 3; kw++)
            m = fmaxf(m, ip[kh * Win + kw]);
    out[((size_t)nc * HoP + oh + opad) * WoP + ow + opad] = m;
}

__global__ void cd_conv_k(const float* __restrict__ Xf, const float* __restrict__ wcd,
                          const float* __restrict__ bcd, float* __restrict__ xc)
{
    int p = blockIdx.x;
    int o = threadIdx.x;
    float acc = bcd[o];
    for (int i = 0; i < 256; i++) {
        const float* wr = wcd + (o * 256 + i) * 3;
        const float* xr = Xf + i * 88;
        if (p > 0)  acc += xr[p - 1] * wr[0];
        acc += xr[p] * wr[1];
        if (p < 87) acc += xr[p + 1] * wr[2];
    }
    xc[o * 88 + p] = acc;
}

__global__ void cd_max_k(const float* __restrict__ xc, float* __restrict__ v)
{
    int o = threadIdx.x;
    float m = -INFINITY;
    for (int p = 0; p < 88; p++) m = fmaxf(m, xc[o * 88 + p]);
    v[o] = m;
}

__global__ void xhat_k(const float* __restrict__ v, const float* __restrict__ wt,
                       const float* __restrict__ bt, float* __restrict__ xhat)
{
    __shared__ float sv[256];
    int o = blockIdx.x;
    int k = threadIdx.x;
    for (int i = threadIdx.x; i < 256; i += blockDim.x) sv[i] = v[i];
    __syncthreads();
    float acc = bt[o];
    for (int i = 0; i < 256; i++)
        acc += sv[i] * wt[((size_t)i * 256 + o) * 88 + k];
    xhat[o * 88 + k] = acc;
}

__global__ void gather_nodes_k(const float* __restrict__ p5, float* __restrict__ nodes)
{
    int idx = blockIdx.x * blockDim.x + threadIdx.x;
    if (idx >= TMN * 256) return;
    int d = idx % 256;
    int n = idx / 256;
    int t = n % 16, m = n / 16;
    nodes[idx] = p5[((size_t)t * 256 + d) * 88 + m];
}

__global__ __launch_bounds__(256)
void rbgemm_k(const float* __restrict__ A, const float* __restrict__ B,
              const float* __restrict__ bias, float* __restrict__ C,
              int M, int N, int K, int flags)
{
    __shared__ float As[16][65];
    __shared__ float Bs[16][64];
    int tid = threadIdx.x;
    int tx = tid & 15;
    int ty = tid >> 4;
    int m0 = blockIdx.y * 64;
    int n0 = blockIdx.x * 64;

    float acc[4][4] = {};

    for (int k0 = 0; k0 < K; k0 += 16) {
        #pragma unroll
        for (int i = 0; i < 4; i++) {
            int e  = tid + i * 256;
            int kk = e & 15;
            int mm = e >> 4;
            int gm = m0 + mm, gk = k0 + kk;
            As[kk][mm] = (gm < M && gk < K) ? A[(size_t)gm * K + gk] : 0.f;
        }
        #pragma unroll
        for (int i = 0; i < 4; i++) {
            int nn = tid & 63;
            int kk = (tid >> 6) + i * 4;
            int gk = k0 + kk, gn = n0 + nn;
            Bs[kk][nn] = (gk < K && gn < N) ? B[(size_t)gk * N + gn] : 0.f;
        }
        __syncthreads();
        #pragma unroll
        for (int kk = 0; kk < 16; kk++) {
            float ra[4], rb[4];
            #pragma unroll
            for (int i = 0; i < 4; i++) ra[i] = As[kk][ty * 4 + i];
            #pragma unroll
            for (int j = 0; j < 4; j++) rb[j] = Bs[kk][tx * 4 + j];
            #pragma unroll
            for (int i = 0; i < 4; i++)
                #pragma unroll
                for (int j = 0; j < 4; j++)
                    acc[i][j] += ra[i] * rb[j];
        }
        __syncthreads();
    }

    #pragma unroll
    for (int i = 0; i < 4; i++) {
        int gm = m0 + ty * 4 + i;
        if (gm >= M) continue;
        #pragma unroll
        for (int j = 0; j < 4; j++) {
            int gn = n0 + tx * 4 + j;
            if (gn >= N) continue;
            float v = acc[i][j];
            if (flags & 1) v += bias[gm];
            if (flags & 2) v += bias[gn];
            if (flags & 4) v = v >= 0.f ? v : 0.01f * v;
            C[(size_t)gm * N + gn] = v;
        }
    }
}

__global__ void a1_reduce_k(const float* __restrict__ Y, float* __restrict__ S, int F)
{
    int f = blockIdx.x * blockDim.x + threadIdx.x;
    int t = blockIdx.y;
    if (f >= F) return;
    float s = 0.f;
    for (int m = 0; m < 88; m++) s += Y[(size_t)(m * 16 + t) * F + f];
    S[t * F + f] = s;
}

__global__ void a1_apply_k(const float* __restrict__ Y, const float* __restrict__ S,
                           const float* __restrict__ bias, float* __restrict__ h, int F)
{
    int idx = blockIdx.x * blockDim.x + threadIdx.x;
    if (idx >= TMN * F) return;
    int f = idx % F;
    int n = idx / F;
    int t = n % 16;
    float val = S[t * F + f] + bias[f];
    if (t == 0) val -= Y[idx];
    h[idx] = val >= 0.f ? val : 0.01f * val;
}

__global__ void v1_k(const float* __restrict__ h2, const float* __restrict__ xhat,
                     float* __restrict__ V1, float* __restrict__ V1t, float* __restrict__ Vx)
{
    int idx = blockIdx.x * blockDim.x + threadIdx.x;
    if (idx >= 256 * 88) return;
    int d = idx % 256;
    int m = idx / 256;
    float mx = -INFINITY;
    #pragma unroll
    for (int t = 0; t < 16; t++) mx = fmaxf(mx, h2[(size_t)(m * 16 + t) * 256 + d]);
    V1[d * 88 + m] = mx;
    V1t[m * 256 + d] = mx;
    Vx[d * 88 + m] = mx + xhat[d * 88 + m];
}

__global__ void attn_k(const float* __restrict__ G, const float* __restrict__ Hh,
                       float* __restrict__ A2)
{
    __shared__ float red[128];
    int j = blockIdx.x;
    int i = threadIdx.x;
    float s = 0.f;
    if (i < 88) {
        for (int d = 0; d < 256; d++) s += Hh[d * 88 + j] * G[d * 88 + i];
    }
    red[i] = (i < 88) ? s : -INFINITY;
    __syncthreads();
    for (int st = 64; st > 0; st >>= 1) {
        if (i < st) red[i] = fmaxf(red[i], red[i + st]);
        __syncthreads();
    }
    float mx = red[0];
    __syncthreads();
    float e = (i < 88) ? expf(s - mx) : 0.f;
    red[i] = e;
    __syncthreads();
    for (int st = 64; st > 0; st >>= 1) {
        if (i < st) red[i] += red[i + st];
        __syncthreads();
    }
    float sum = red[0];
    if (i < 88) A2[j * 88 + i] = e / sum;
}

__global__ void final_dot_k(const float* __restrict__ Xf, const float* __restrict__ V2t,
                            float* __restrict__ out)
{
    __shared__ float red[256];
    float acc = 0.f;
    for (int e = threadIdx.x; e < 256 * 88; e += 256) {
        int d = e / 88, m = e % 88;
        acc += Xf[e] * V2t[m * 256 + d];
    }
    red[threadIdx.x] = acc;
    __syncthreads();
    for (int st = 128; st > 0; st >>= 1) {
        if (threadIdx.x < st) red[threadIdx.x] += red[threadIdx.x + st];
        __syncthreads();
    }
    if (threadIdx.x == 0) out[0] = red[0];
}

// ---------------- host ----------------
static float* symaddr(const void* s)
{
    void* p = nullptr;
    cudaGetSymbolAddress(&p, s);
    return (float*)p;
}
static __nv_bfloat16* symaddr_bf(const void* s)
{
    void* p = nullptr;
    cudaGetSymbolAddress(&p, s);
    return (__nv_bfloat16*)p;
}

extern "C" void kernel_launch(void* const* d_in, const int* in_sizes, int n_in,
                              void* d_out, int out_size)
{
    const float* search    = (const float*)d_in[0];
    const float* exemplars = (const float*)d_in[1];
    const float* aw1 = (const float*)d_in[2];  const float* ab1 = (const float*)d_in[3];
    const float* aw2 = (const float*)d_in[4];  const float* ab2 = (const float*)d_in[5];
    const float* aw3 = (const float*)d_in[6];  const float* ab3 = (const float*)d_in[7];
    const float* aw4 = (const float*)d_in[8];  const float* ab4 = (const float*)d_in[9];
    const float* aw5 = (const float*)d_in[10]; const float* ab5 = (const float*)d_in[11];
    const float* wcd = (const float*)d_in[12]; const float* bcd = (const float*)d_in[13];
    const float* wt  = (const float*)d_in[14]; const float* bt  = (const float*)d_in[15];
    const float* ws1 = (const float*)d_in[16]; const float* bs1 = (const float*)d_in[17];
    const float* ws2 = (const float*)d_in[18]; const float* bs2 = (const float*)d_in[19];
    const float* wg  = (const float*)d_in[20]; const float* bg  = (const float*)d_in[21];
    const float* wh  = (const float*)d_in[22]; const float* bh  = (const float*)d_in[23];
    const float* wc1 = (const float*)d_in[24]; const float* bc1 = (const float*)d_in[25];
    const float* wc2 = (const float*)d_in[26]; const float* bc2 = (const float*)d_in[27];

    float* p_in  = symaddr(g_in);
    float* p_c1  = symaddr(g_c1);
    float* p_p1  = symaddr(g_p1);
    float* p_c2  = symaddr(g_c2);
    float* p_p2  = symaddr(g_p2);
    float* p_c3  = symaddr(g_c3);
    float* p_c4  = symaddr(g_c4);
    float* p_c5  = symaddr(g_c5);
    float* p_p5  = symaddr(g_p5);
    float* p_xc  = symaddr(g_xc);
    float* p_v   = symaddr(g_v);
    float* p_xh  = symaddr(g_xhat);
    float* p_nd  = symaddr(g_nodes);
    float* p_Y1  = symaddr(g_Y1);
    float* p_S   = symaddr(g_S);
    float* p_h1  = symaddr(g_h1);
    float* p_Y2  = symaddr(g_Y2);
    float* p_h2  = symaddr(g_h2);
    float* p_V1  = symaddr(g_V1);
    float* p_V1t = symaddr(g_V1t);
    float* p_Vx  = symaddr(g_Vx);
    float* p_G   = symaddr(g_G);
    float* p_Hh  = symaddr(g_Hh);
    float* p_A2  = symaddr(g_A2);
    float* p_xw  = symaddr(g_xw);
    float* p_c1m = symaddr(g_c1m);
    float* p_cw  = symaddr(g_cw);
    float* p_V2t = symaddr(g_V2t);
    __nv_bfloat16* pAhi = symaddr_bf(g_Ahi);
    __nv_bfloat16* pAlo = symaddr_bf(g_Alo);
    __nv_bfloat16* pBhi = symaddr_bf(g_Bhi);
    __nv_bfloat16* pBlo = symaddr_bf(g_Blo);

    cudaFuncSetAttribute(mmaconv64_k, cudaFuncAttributeMaxDynamicSharedMemorySize, SMEM_G1);
    cudaFuncSetAttribute(mmaconv_imp_k, cudaFuncAttributeMaxDynamicSharedMemorySize, SMEM_G2);

    // zero padded buffers (borders must be 0 every replay)
    cudaMemsetAsync(p_in, 0, sizeof(float) * ((size_t)N_IMG * 3 * H0P * W0P + TAILPAD), 0);
    cudaMemsetAsync(p_p1, 0, sizeof(float) * ((size_t)N_IMG * C1o * P1HP * P1WP + TAILPAD), 0);
    cudaMemsetAsync(p_p2, 0, sizeof(float) * ((size_t)N_IMG * C2o * P2HP * P2WP + TAILPAD), 0);
    cudaMemsetAsync(p_c3, 0, sizeof(float) * ((size_t)N_IMG * C3o * P2HP * P2WP + TAILPAD), 0);
    cudaMemsetAsync(p_c4, 0, sizeof(float) * ((size_t)N_IMG * C4o * P2HP * P2WP + TAILPAD), 0);

    // assemble padded input batch
    {
        int tot = 16 * 3 * H0 * W0;
        pad_copy_k<<<(tot + 127) / 128, 128>>>(exemplars, p_in, 16, 0);
        tot = 3 * H0 * W0;
        pad_copy_k<<<(tot + 127) / 128, 128>>>(search, p_in, 1, 16);
    }

    // ---- conv1 (explicit im2col, 64x128 tile GEMM): M=64, K=384(pad), NP=17*95*71 ----
    {
        const int KP = 384, NP = N_IMG * H1 * W1;
        wsplit_pad_k<<<(C1o * KP + 255) / 256, 256>>>(aw1, pAhi, pAlo, C1o, 363, KP);
        int tot = NP * KP;
        im2col_t<3, 11, 4, H0P, W0P, H1, W1, 384><<<(tot + 255) / 256, 256>>>(p_in, pBhi, pBlo);
        mmaconv64_k<<<(NP + 127) / 128, 256, SMEM_G1>>>(
            pAhi, pAlo, pBhi, pBlo, ab1, p_c1, C1o, NP, KP, H1, W1, H1, W1, 0);
    }
    {
        int tot = N_IMG * C1o * P1H * P1W;
        maxpool_k<<<(tot + 127) / 128, 128>>>(p_c1, p_p1, N_IMG * C1o, H1, W1, P1H, P1W, P1HP, P1WP, 2);
    }

    // ---- p1 -> NHWC bf16 ----
    {
        const int NPIX = P1HP * P1WP;   // 1989
        nchw2nhwc_k<<<dim3((NPIX + 31) / 32, C1o / 32, N_IMG), dim3(32, 8)>>>(p_p1, pBhi, pBlo, C1o, NPIX);
    }

    // ---- conv2 (implicit): M=192, K=1600, CIN=64, KD=5 ----
    {
        const int K = 1600, NP = N_IMG * H2 * W2;
        wsplit_reorder_k<<<(C2o * K + 255) / 256, 256>>>(aw2, pAhi, pAlo, C2o, 64, 25);
        mmaconv_imp_k<<<dim3((NP + 63) / 64, 2), 256, SMEM_G2>>>(
            pAhi, pAlo, pBhi, pBlo, ab2, p_c2, C2o, NP, K, 64, 5,
            P1HP, P1WP, H2, W2, H2, W2, 0);
    }
    {
        int tot = N_IMG * C2o * P2H * P2W;
        maxpool_k<<<(tot + 127) / 128, 128>>>(p_c2, p_p2, N_IMG * C2o, H2, W2, P2H, P2W, P2HP, P2WP, 1);
    }

    // ---- p2 -> NHWC ----
    {
        const int NPIX = P2HP * P2WP;   // 475
        nchw2nhwc_k<<<dim3((NPIX + 31) / 32, C2o / 32, N_IMG), dim3(32, 8)>>>(p_p2, pBhi, pBlo, C2o, NPIX);
    }

    // ---- conv3 (implicit): M=384, K=1728, CIN=192 ----
    {
        const int K = 1728, NP = N_IMG * P2H * P2W;
        wsplit_reorder_k<<<(C3o * K + 255) / 256, 256>>>(aw3, pAhi, pAlo, C3o, 192, 9);
        mmaconv_imp_k<<<dim3((NP + 63) / 64, 3), 256, SMEM_G2>>>(
            pAhi, pAlo, pBhi, pBlo, ab3, p_c3, C3o, NP, K, 192, 3,
            P2HP, P2WP, P2H, P2W, P2HP, P2WP, 1);
    }

    // ---- c3 -> NHWC ----
    {
        const int NPIX = P2HP * P2WP;
        nchw2nhwc_k<<<dim3((NPIX + 31) / 32, C3o / 32, N_IMG), dim3(32, 8)>>>(p_c3, pBhi, pBlo, C3o, NPIX);
    }

    // ---- conv4 (implicit): M=256, K=3456, CIN=384 ----
    {
        const int K = 3456, NP = N_IMG * P2H * P2W;
        wsplit_reorder_k<<<(C4o * K + 255) / 256, 256>>>(aw4, pAhi, pAlo, C4o, 384, 9);
        mmaconv_imp_k<<<dim3((NP + 63) / 64, 2), 256, SMEM_G2>>>(
            pAhi, pAlo, pBhi, pBlo, ab4, p_c4, C4o, NP, K, 384, 3,
            P2HP, P2WP, P2H, P2W, P2HP, P2WP, 1);
    }

    // ---- c4 -> NHWC ----
    {
        const int NPIX = P2HP * P2WP;
        nchw2nhwc_k<<<dim3((NPIX + 31) / 32, C4o / 32, N_IMG), dim3(32, 8)>>>(p_c4, pBhi, pBlo, C4o, NPIX);
    }

    // ---- conv5 (implicit): M=256, K=2304, CIN=256, out unpadded ----
    {
        const int K = 2304, NP = N_IMG * P2H * P2W;
        wsplit_reorder_k<<<(C5o * K + 255) / 256, 256>>>(aw5, pAhi, pAlo, C5o, 256, 9);
        mmaconv_imp_k<<<dim3((NP + 63) / 64, 2), 256, SMEM_G2>>>(
            pAhi, pAlo, pBhi, pBlo, ab5, p_c5, C5o, NP, K, 256, 3,
            P2HP, P2WP, P2H, P2W, H5, W5, 0);
    }
    {
        int tot = N_IMG * C5o * P5H * P5W;
        maxpool_k<<<(tot + 127) / 128, 128>>>(p_c5, p_p5, N_IMG * C5o, H5, W5, P5H, P5W, P5H, P5W, 0);
    }

    const float* Xf = p_p5 + (size_t)16 * 256 * 88;

    // ---- conv_deconv branch ----
    cd_conv_k<<<88, 256>>>(Xf, wcd, bcd, p_xc);
    cd_max_k<<<1, 256>>>(p_xc, p_v);
    xhat_k<<<256, 88>>>(p_v, wt, bt, p_xh);

    // ---- spatiotemporal GCN ----
    gather_nodes_k<<<(TMN * 256 + 127) / 128, 128>>>(p_p5, p_nd);
    rbgemm_k<<<dim3(512 / 64, TMN / 64), 256>>>(p_nd, ws1, nullptr, p_Y1, TMN, 512, 256, 0);
    a1_reduce_k<<<dim3(4, 16), 128>>>(p_Y1, p_S, 512);
    a1_apply_k<<<(TMN * 512 + 255) / 256, 256>>>(p_Y1, p_S, bs1, p_h1, 512);
    rbgemm_k<<<dim3(256 / 64, TMN / 64), 256>>>(p_h1, ws2, nullptr, p_Y2, TMN, 256, 512, 0);
    a1_reduce_k<<<dim3(2, 16), 128>>>(p_Y2, p_S, 256);
    a1_apply_k<<<(TMN * 256 + 255) / 256, 256>>>(p_Y2, p_S, bs2, p_h2, 256);
    v1_k<<<(256 * 88 + 255) / 256, 256>>>(p_h2, p_xh, p_V1, p_V1t, p_Vx);

    // ---- dynamic cross-track graph ----
    rbgemm_k<<<dim3((88 + 63) / 64, 256 / 64), 256>>>(wg, p_Vx, bg, p_G, 256, 88, 256, 1);
    rbgemm_k<<<dim3((88 + 63) / 64, 256 / 64), 256>>>(wh, p_Vx, bh, p_Hh, 256, 88, 256, 1);
    attn_k<<<88, 128>>>(p_G, p_Hh, p_A2);

    // ---- ct GCN ----
    rbgemm_k<<<dim3(384 / 64, (88 + 63) / 64), 256>>>(p_V1t, wc1, nullptr, p_xw, 88, 384, 256, 0);
    rbgemm_k<<<dim3(384 / 64, (88 + 63) / 64), 256>>>(p_A2, p_xw, bc1, p_c1m, 88, 384, 88, 2 | 4);
    rbgemm_k<<<dim3(256 / 64, (88 + 63) / 64), 256>>>(p_c1m, wc2, nullptr, p_cw, 88, 256, 384, 0);
    rbgemm_k<<<dim3(256 / 64, (88 + 63) / 64), 256>>>(p_A2, p_cw, bc2, p_V2t, 88, 256, 88, 2 | 4);

    // ---- final correlation ----
    final_dot_k<<<1, 256>>>(Xf, p_V2t, (float*)d_out);
}